// round 11
// baseline (speedup 1.0000x reference)
#include <cuda_runtime.h>
#include <cuda_bf16.h>
#include <cuda_fp16.h>
#include <stdint.h>
#include <math.h>

#define NMAX 50048
#define EMAX 600064

// ---------------- scratch (static __device__ — no allocation) ----------------
__device__ float  g_qp [NMAX * 128];
__device__ __half g_rkh[2][NMAX * 128];
__device__ __half g_rvh[2][NMAX * 128];
__device__ float  g_outp2[2][NMAX * 128];   // per-relation normalized aggregates
__device__ float  g_cw[4][128 * 128];
__device__ uint2  g_wI[5][128 * 64];        // [n][k-pair] interleaved (hi, lo) bf16x2
__device__ int    g_deg[2][NMAX];
__device__ int    g_cur[2][NMAX];
__device__ int    g_off[2][NMAX + 1];
__device__ int    g_csr[2][EMAX];

// ---------------- compose weights + zero counters ------------------------------
__global__ void compose_kernel(const float* __restrict__ A0, const float* __restrict__ B0,
                               const float* __restrict__ A1, const float* __restrict__ B1,
                               const float* __restrict__ A2, const float* __restrict__ B2,
                               const float* __restrict__ A3, const float* __restrict__ B3,
                               int n) {
    int gid = (blockIdx.y * gridDim.x + blockIdx.x) * blockDim.x + threadIdx.x;
    if (gid < n) {
        g_deg[0][gid] = 0; g_deg[1][gid] = 0;
        g_cur[0][gid] = 0; g_cur[1][gid] = 0;
    }

    const float* A; const float* B;
    switch (blockIdx.y) {
        case 0: A = A0; B = B0; break;
        case 1: A = A1; B = B1; break;
        case 2: A = A2; B = B2; break;
        default: A = A3; B = B3; break;
    }
    float* C = g_cw[blockIdx.y];
    int i = blockIdx.x;
    int j = threadIdx.x;
    __shared__ float As[128];
    As[j] = A[i * 128 + j];
    __syncthreads();
    float acc = 0.f;
#pragma unroll 8
    for (int k = 0; k < 128; k++) acc += As[k] * B[k * 128 + j];
    C[i * 128 + j] = acc;
}

// ---------------- weight split: [k][n] f32 -> [n][k-pair] uint2 (hi,lo) --------
__device__ __forceinline__ uint32_t pack_bf2(float a, float b) {
    __nv_bfloat162 h = __floats2bfloat162_rn(a, b);
    return *(uint32_t*)&h;
}

__global__ void convert_w_kernel(const float* __restrict__ wq_p) {
    int s = blockIdx.y;
    const float* src = (s == 0) ? wq_p : g_cw[s - 1];
    int i = blockIdx.x * blockDim.x + threadIdx.x;   // 0..8191
    int nn = i >> 6, kp = i & 63;
    float v0 = src[(2 * kp) * 128 + nn];
    float v1 = src[(2 * kp + 1) * 128 + nn];
    float h0 = __bfloat162float(__float2bfloat16(v0));
    float h1 = __bfloat162float(__float2bfloat16(v1));
    uint2 w;
    w.x = pack_bf2(h0, h1);
    w.y = pack_bf2(v0 - h0, v1 - h1);
    g_wI[s][nn * 64 + kp] = w;
}

// ---------------- tensor-core GEMM (bf16x3), 5 products fused ------------------
#define SMS 20

__global__ __launch_bounds__(256, 2) void mma_gemm5(
    const float4* __restrict__ xa4, const float4* __restrict__ xp4, int nrows) {
    int slice = blockIdx.z;
    int chalf = blockIdx.y;
    const float4* Xf4 = (slice == 1 || slice == 2) ? xa4 : xp4;
    const uint2* WI = g_wI[slice];

    __shared__ uint2 AhL[128 * SMS];
    __shared__ uint2 BhL[64 * SMS];

    int tid = threadIdx.x;
    int lane = tid & 31;
    int warp = tid >> 5;
    int wm = warp & 3;
    int wn = warp >> 2;
    int row0 = blockIdx.x * 128;

    float acc[2][4][4];
#pragma unroll
    for (int mt = 0; mt < 2; mt++)
#pragma unroll
        for (int nt = 0; nt < 4; nt++)
#pragma unroll
            for (int r = 0; r < 4; r++) acc[mt][nt][r] = 0.f;

    int lq = lane >> 2;
    int lc = lane & 3;

    for (int ch = 0; ch < 4; ch++) {
#pragma unroll
        for (int it = 0; it < 4; it++) {
            int lin = it * 256 + tid;
            int r = lin >> 3, f4 = lin & 7;
            int gr = row0 + r;
            float4 x4 = make_float4(0.f, 0.f, 0.f, 0.f);
            if (gr < nrows) x4 = Xf4[(size_t)gr * 32 + ch * 8 + f4];
            float h0 = __bfloat162float(__float2bfloat16(x4.x));
            float h1 = __bfloat162float(__float2bfloat16(x4.y));
            float h2 = __bfloat162float(__float2bfloat16(x4.z));
            float h3 = __bfloat162float(__float2bfloat16(x4.w));
            uint4 o;
            o.x = pack_bf2(h0, h1);
            o.y = pack_bf2(x4.x - h0, x4.y - h1);
            o.z = pack_bf2(h2, h3);
            o.w = pack_bf2(x4.z - h2, x4.w - h3);
            *(uint4*)&AhL[r * SMS + f4 * 2] = o;
        }
#pragma unroll
        for (int it = 0; it < 2; it++) {
            int lin = it * 256 + tid;
            int r = lin >> 3, p = lin & 7;
            uint4 w = *(const uint4*)&WI[(size_t)(chalf * 64 + r) * 64 + ch * 16 + p * 2];
            *(uint4*)&BhL[r * SMS + p * 2] = w;
        }
        __syncthreads();

#pragma unroll
        for (int s = 0; s < 2; s++) {
            int kb = s * 8;
            uint32_t ah[2][4], al[2][4];
#pragma unroll
            for (int mt = 0; mt < 2; mt++) {
                int rbase = wm * 32 + mt * 16;
                int i0 = (rbase + lq) * SMS + kb + lc;
                int i1 = (rbase + lq + 8) * SMS + kb + lc;
                uint2 a0 = AhL[i0], a1 = AhL[i1];
                uint2 a2 = AhL[i0 + 4], a3 = AhL[i1 + 4];
                ah[mt][0] = a0.x; ah[mt][1] = a1.x; ah[mt][2] = a2.x; ah[mt][3] = a3.x;
                al[mt][0] = a0.y; al[mt][1] = a1.y; al[mt][2] = a2.y; al[mt][3] = a3.y;
            }
#pragma unroll
            for (int nt = 0; nt < 4; nt++) {
                int nb = (wn * 32 + nt * 8 + lq) * SMS + kb + lc;
                uint2 b0 = BhL[nb], b1 = BhL[nb + 4];
                uint32_t bh0 = b0.x, bl0 = b0.y, bh1 = b1.x, bl1 = b1.y;
#pragma unroll
                for (int mt = 0; mt < 2; mt++) {
                    float* d = acc[mt][nt];
                    asm volatile(
                        "mma.sync.aligned.m16n8k16.row.col.f32.bf16.bf16.f32 "
                        "{%0,%1,%2,%3}, {%4,%5,%6,%7}, {%8,%9}, {%0,%1,%2,%3};"
                        : "+f"(d[0]), "+f"(d[1]), "+f"(d[2]), "+f"(d[3])
                        : "r"(ah[mt][0]), "r"(ah[mt][1]), "r"(ah[mt][2]), "r"(ah[mt][3]),
                          "r"(bh0), "r"(bh1));
                    asm volatile(
                        "mma.sync.aligned.m16n8k16.row.col.f32.bf16.bf16.f32 "
                        "{%0,%1,%2,%3}, {%4,%5,%6,%7}, {%8,%9}, {%0,%1,%2,%3};"
                        : "+f"(d[0]), "+f"(d[1]), "+f"(d[2]), "+f"(d[3])
                        : "r"(ah[mt][0]), "r"(ah[mt][1]), "r"(ah[mt][2]), "r"(ah[mt][3]),
                          "r"(bl0), "r"(bl1));
                    asm volatile(
                        "mma.sync.aligned.m16n8k16.row.col.f32.bf16.bf16.f32 "
                        "{%0,%1,%2,%3}, {%4,%5,%6,%7}, {%8,%9}, {%0,%1,%2,%3};"
                        : "+f"(d[0]), "+f"(d[1]), "+f"(d[2]), "+f"(d[3])
                        : "r"(al[mt][0]), "r"(al[mt][1]), "r"(al[mt][2]), "r"(al[mt][3]),
                          "r"(bh0), "r"(bh1));
                }
            }
        }
        __syncthreads();
    }

    if (slice == 0) {
        float* Y = g_qp;
#pragma unroll
        for (int mt = 0; mt < 2; mt++)
#pragma unroll
            for (int nt = 0; nt < 4; nt++) {
                int col = chalf * 64 + wn * 32 + nt * 8 + lc * 2;
                int r0 = row0 + wm * 32 + mt * 16 + lq;
                if (r0 < nrows)
                    *(float2*)(Y + (size_t)r0 * 128 + col) =
                        make_float2(acc[mt][nt][0], acc[mt][nt][1]);
                int r1 = r0 + 8;
                if (r1 < nrows)
                    *(float2*)(Y + (size_t)r1 * 128 + col) =
                        make_float2(acc[mt][nt][2], acc[mt][nt][3]);
            }
    } else {
        __half* Y;
        switch (slice) {
            case 1: Y = g_rkh[0]; break;
            case 2: Y = g_rvh[0]; break;
            case 3: Y = g_rkh[1]; break;
            default:Y = g_rvh[1]; break;
        }
#pragma unroll
        for (int mt = 0; mt < 2; mt++)
#pragma unroll
            for (int nt = 0; nt < 4; nt++) {
                int col = chalf * 64 + wn * 32 + nt * 8 + lc * 2;
                int r0 = row0 + wm * 32 + mt * 16 + lq;
                if (r0 < nrows)
                    *(__half2*)(Y + (size_t)r0 * 128 + col) =
                        __float22half2_rn(make_float2(acc[mt][nt][0], acc[mt][nt][1]));
                int r1 = r0 + 8;
                if (r1 < nrows)
                    *(__half2*)(Y + (size_t)r1 * 128 + col) =
                        __float22half2_rn(make_float2(acc[mt][nt][2], acc[mt][nt][3]));
            }
    }
}

// ---------------- CSR build ----------------------------------------------------
__global__ void hist2_kernel(const int* __restrict__ e_w, int Ew,
                             const int* __restrict__ e_c, int Ec) {
    int rel = blockIdx.y;
    const int* e = rel ? e_c : e_w;
    int E = rel ? Ec : Ew;
    int i = blockIdx.x * blockDim.x + threadIdx.x;
    if (i < E) atomicAdd(&g_deg[rel][e[E + i]], 1);
}

__global__ void scan_kernel(int n) {
    int rel = blockIdx.x;
    __shared__ int sm[1024];
    int tid = threadIdx.x;
    int C = (n + 1023) / 1024;
    int b = tid * C;
    int e = b + C; if (e > n) e = n;
    if (b > n) b = n;
    int s = 0;
    for (int i = b; i < e; i++) s += g_deg[rel][i];
    sm[tid] = s;
    __syncthreads();
#pragma unroll
    for (int ofs = 1; ofs < 1024; ofs <<= 1) {
        int t = (tid >= ofs) ? sm[tid - ofs] : 0;
        __syncthreads();
        sm[tid] += t;
        __syncthreads();
    }
    int run = sm[tid] - s;
    for (int i = b; i < e; i++) { int d = g_deg[rel][i]; g_off[rel][i] = run; run += d; }
    if (e == n) g_off[rel][n] = run;
}

__global__ void scatter2_kernel(const int* __restrict__ e_w, int Ew,
                                const int* __restrict__ e_c, int Ec) {
    int rel = blockIdx.y;
    const int* e = rel ? e_c : e_w;
    int E = rel ? Ec : Ew;
    int i = blockIdx.x * blockDim.x + threadIdx.x;
    if (i < E) {
        int src = e[i];
        int dst = e[E + i];
        int p = atomicAdd(&g_cur[rel][dst], 1);
        g_csr[rel][g_off[rel][dst] + p] = src;
    }
}

// ---------------- aggregation: one warp per (dst, relation) --------------------
// Max-free softmax (scores ~N(0,1), no overflow). Index prefetch pipelining:
// next iteration's CSR indices load while current gathers are in flight.
__device__ __forceinline__ float4 half4_to_float4(uint2 u) {
    __half2 h0 = *(__half2*)&u.x;
    __half2 h1 = *(__half2*)&u.y;
    float2 f0 = __half22float2(h0);
    float2 f1 = __half22float2(h1);
    return make_float4(f0.x, f0.y, f1.x, f1.y);
}

__device__ __forceinline__ float head_dot(float4 q4, float4 k4) {
    float p = q4.x*k4.x + q4.y*k4.y + q4.z*k4.z + q4.w*k4.w;
    p += __shfl_xor_sync(0xFFFFFFFFu, p, 1);
    p += __shfl_xor_sync(0xFFFFFFFFu, p, 2);
    p += __shfl_xor_sync(0xFFFFFFFFu, p, 4);
    return p;
}

__global__ __launch_bounds__(256) void aggregate_kernel(int n) {
    int rel = blockIdx.y;
    int dst = (blockIdx.x * blockDim.x + threadIdx.x) >> 5;
    if (dst >= n) return;
    int lane = threadIdx.x & 31;

    const __half* __restrict__ rk = g_rkh[rel];
    const __half* __restrict__ rv = g_rvh[rel];
    const int*    __restrict__ csr = g_csr[rel];

    int beg = g_off[rel][dst];
    int end = g_off[rel][dst + 1];
    float* o = g_outp2[rel] + (size_t)dst * 128 + lane * 4;

    if (beg == end) {
        *(float4*)o = make_float4(0.f, 0.f, 0.f, 0.f);
        return;
    }

    float4 q4 = *(const float4*)(g_qp + (size_t)dst * 128 + lane * 4);
    const float scale = 0.17677669529663687f;   // 1/sqrt(32)

    float s0a = 0.f, s1a = 0.f;
    float4 A0 = make_float4(0.f,0.f,0.f,0.f);
    float4 A1 = make_float4(0.f,0.f,0.f,0.f);

    int nedge = end - beg;
    int nfull = nedge & ~3;

    int i0 = 0, i1 = 0, i2 = 0, i3 = 0;
    if (nfull) {
        i0 = csr[beg]; i1 = csr[beg+1]; i2 = csr[beg+2]; i3 = csr[beg+3];
    }
    for (int b = 0; b < nfull; b += 4) {
        // prefetch next indices before the gathers' results are consumed
        int j0, j1, j2, j3;
        bool more = (b + 4 < nfull);
        if (more) {
            j0 = csr[beg+b+4]; j1 = csr[beg+b+5];
            j2 = csr[beg+b+6]; j3 = csr[beg+b+7];
        }
        float4 k0 = half4_to_float4(*(const uint2*)(rk + (size_t)i0 * 128 + lane * 4));
        float4 k1 = half4_to_float4(*(const uint2*)(rk + (size_t)i1 * 128 + lane * 4));
        float4 k2 = half4_to_float4(*(const uint2*)(rk + (size_t)i2 * 128 + lane * 4));
        float4 k3 = half4_to_float4(*(const uint2*)(rk + (size_t)i3 * 128 + lane * 4));
        float4 v0 = half4_to_float4(*(const uint2*)(rv + (size_t)i0 * 128 + lane * 4));
        float4 v1 = half4_to_float4(*(const uint2*)(rv + (size_t)i1 * 128 + lane * 4));
        float4 v2 = half4_to_float4(*(const uint2*)(rv + (size_t)i2 * 128 + lane * 4));
        float4 v3 = half4_to_float4(*(const uint2*)(rv + (size_t)i3 * 128 + lane * 4));
        float p0 = __expf(head_dot(q4, k0) * scale);
        float p1 = __expf(head_dot(q4, k1) * scale);
        float p2 = __expf(head_dot(q4, k2) * scale);
        float p3 = __expf(head_dot(q4, k3) * scale);
        s0a += p0 + p2;
        s1a += p1 + p3;
        A0.x += p0*v0.x + p2*v2.x;  A1.x += p1*v1.x + p3*v3.x;
        A0.y += p0*v0.y + p2*v2.y;  A1.y += p1*v1.y + p3*v3.y;
        A0.z += p0*v0.z + p2*v2.z;  A1.z += p1*v1.z + p3*v3.z;
        A0.w += p0*v0.w + p2*v2.w;  A1.w += p1*v1.w + p3*v3.w;
        i0 = j0; i1 = j1; i2 = j2; i3 = j3;
    }
    for (int e = beg + nfull; e < end; e++) {
        int ix = csr[e];
        float4 k0 = half4_to_float4(*(const uint2*)(rk + (size_t)ix * 128 + lane * 4));
        float4 v0 = half4_to_float4(*(const uint2*)(rv + (size_t)ix * 128 + lane * 4));
        float p0 = __expf(head_dot(q4, k0) * scale);
        s0a += p0;
        A0.x += p0*v0.x; A0.y += p0*v0.y; A0.z += p0*v0.z; A0.w += p0*v0.w;
    }

    float inv = 1.f / (s0a + s1a);
    float4 r;
    r.x = (A0.x + A1.x) * inv;
    r.y = (A0.y + A1.y) * inv;
    r.z = (A0.z + A1.z) * inv;
    r.w = (A0.w + A1.w) * inv;
    *(float4*)o = r;
}

// ---------------- final projections -------------------------------------------
__global__ __launch_bounds__(256) void final_kernel(
    const float* __restrict__ Xa, const float* __restrict__ Xp,
    const float* __restrict__ Wr_a, const float* __restrict__ Wo_p,
    const float* __restrict__ Wr_p, const float* __restrict__ bo_a,
    const float* __restrict__ bo_p, float* __restrict__ out, int n) {
    int type = blockIdx.y;
    __shared__ float Ws[2 * 128 * 32];
    if (type == 0) {
        for (int i = threadIdx.x; i < 4096; i += blockDim.x) Ws[i] = Wr_a[i];
    } else {
        for (int i = threadIdx.x; i < 4096; i += blockDim.x) Ws[i] = Wo_p[i];
        for (int i = threadIdx.x; i < 4096; i += blockDim.x) Ws[4096 + i] = Wr_p[i];
    }
    __syncthreads();
    int warp = blockIdx.x * (blockDim.x >> 5) + (threadIdx.x >> 5);
    int lane = threadIdx.x & 31;
    if (warp >= n) return;

    if (type == 0) {
        const float4* xr4 = (const float4*)(Xa + (size_t)warp * 128);
        float a0 = 0.f, a1 = 0.f;
#pragma unroll
        for (int k4 = 0; k4 < 32; k4++) {
            float4 x4 = xr4[k4];
            a0 += x4.x * Ws[(k4*4+0)*32 + lane] + x4.y * Ws[(k4*4+1)*32 + lane];
            a1 += x4.z * Ws[(k4*4+2)*32 + lane] + x4.w * Ws[(k4*4+3)*32 + lane];
        }
        out[(size_t)warp * 32 + lane] = bo_a[lane] + a0 + a1;
    } else {
        const float4* o0 = (const float4*)(g_outp2[0] + (size_t)warp * 128);
        const float4* o1 = (const float4*)(g_outp2[1] + (size_t)warp * 128);
        const float4* xr4 = (const float4*)(Xp + (size_t)warp * 128);
        float a0 = 0.f, a1 = 0.f;
#pragma unroll
        for (int k4 = 0; k4 < 32; k4++) {
            float4 u = o0[k4];
            float4 v = o1[k4];
            float4 x4 = make_float4(u.x + v.x, u.y + v.y, u.z + v.z, u.w + v.w);
            a0 += x4.x * Ws[(k4*4+0)*32 + lane] + x4.y * Ws[(k4*4+1)*32 + lane];
            a1 += x4.z * Ws[(k4*4+2)*32 + lane] + x4.w * Ws[(k4*4+3)*32 + lane];
        }
#pragma unroll
        for (int k4 = 0; k4 < 32; k4++) {
            float4 x4 = xr4[k4];
            a0 += x4.x * Ws[4096 + (k4*4+0)*32 + lane] + x4.y * Ws[4096 + (k4*4+1)*32 + lane];
            a1 += x4.z * Ws[4096 + (k4*4+2)*32 + lane] + x4.w * Ws[4096 + (k4*4+3)*32 + lane];
        }
        out[(size_t)(n + warp) * 32 + lane] = bo_p[lane] + a0 + a1;
    }
}

// ---------------- launch --------------------------------------------------------
extern "C" void kernel_launch(void* const* d_in, const int* in_sizes, int n_in,
                              void* d_out, int out_size) {
    const float* x_a   = (const float*)d_in[0];
    const float* x_p   = (const float*)d_in[1];
    const int*   e_w   = (const int*)d_in[2];
    const int*   e_c   = (const int*)d_in[3];
    const float* wk_a  = (const float*)d_in[5];
    const float* wv_a  = (const float*)d_in[6];
    const float* wq_p  = (const float*)d_in[7];
    const float* wk_p  = (const float*)d_in[8];
    const float* wv_p  = (const float*)d_in[9];
    const float* wrk_w = (const float*)d_in[10];
    const float* wrv_w = (const float*)d_in[11];
    const float* wrk_c = (const float*)d_in[12];
    const float* wrv_c = (const float*)d_in[13];
    const float* bo_a  = (const float*)d_in[15];
    const float* wo_p  = (const float*)d_in[16];
    const float* bo_p  = (const float*)d_in[17];
    const float* wr_a  = (const float*)d_in[18];
    const float* wr_p  = (const float*)d_in[19];
    float* out = (float*)d_out;

    int n  = in_sizes[0] / 128;
    int Ew = in_sizes[2] / 2;
    int Ec = in_sizes[3] / 2;

    // mma_gemm5 kept in the 4th launch slot (ncu capture)
    compose_kernel<<<dim3(128, 4), 128>>>(wk_a, wrk_w, wv_a, wrv_w,
                                          wk_p, wrk_c, wv_p, wrv_c, n);
    convert_w_kernel<<<dim3(32, 5), 256>>>(wq_p);
    int geb = (((Ew > Ec) ? Ew : Ec) + 255) / 256;
    hist2_kernel<<<dim3(geb, 2), 256>>>(e_w, Ew, e_c, Ec);

    int gb = (n + 127) / 128;
    mma_gemm5<<<dim3(gb, 2, 5), 256>>>((const float4*)x_a, (const float4*)x_p, n);

    scan_kernel<<<2, 1024>>>(n);
    scatter2_kernel<<<dim3(geb, 2), 256>>>(e_w, Ew, e_c, Ec);

    int ga = (n + 7) / 8;
    aggregate_kernel<<<dim3(ga, 2), 256>>>(n);

    int gf = (n + 7) / 8;
    final_kernel<<<dim3(gf, 2), 256>>>(x_a, x_p, wr_a, wo_p, wr_p,
                                       bo_a, bo_p, out, n);
}

// round 13
// speedup vs baseline: 1.0385x; 1.0385x over previous
#include <cuda_runtime.h>
#include <cuda_bf16.h>
#include <cuda_fp16.h>
#include <stdint.h>
#include <math.h>

#define NMAX 50048
#define EMAX 600064

// ---------------- scratch (static __device__ — no allocation) ----------------
// NOTE: g_deg/g_cur start zero (.bss) and are re-zeroed at the END of every
// kernel_launch (final_kernel y==2 plane), so each call/replay sees zeros.
__device__ float  g_qp [NMAX * 128];
__device__ __half g_rkh[2][NMAX * 128];
__device__ __half g_rvh[2][NMAX * 128];
__device__ float  g_outp[NMAX * 128];
__device__ uint2  g_wI[5][128 * 64];      // [n][k-pair] interleaved (hi, lo) bf16x2
__device__ int    g_deg[2][NMAX];
__device__ int    g_cur[2][NMAX];
__device__ int    g_off[2][NMAX + 1];
__device__ int    g_csr[2][EMAX];

__device__ __forceinline__ uint32_t pack_bf2(float a, float b) {
    __nv_bfloat162 h = __floats2bfloat162_rn(a, b);
    return *(uint32_t*)&h;
}

// ---------------- launch 1: hist (z=0)  +  compose & weight-split (z=1) -------
__global__ __launch_bounds__(256) void fusedA_kernel(
    const int* __restrict__ e_w, int Ew, const int* __restrict__ e_c, int Ec,
    const float* __restrict__ wq_p,
    const float* __restrict__ wk_a, const float* __restrict__ wv_a,
    const float* __restrict__ wk_p, const float* __restrict__ wv_p,
    const float* __restrict__ wrk_w, const float* __restrict__ wrv_w,
    const float* __restrict__ wrk_c, const float* __restrict__ wrv_c) {
    int tid = threadIdx.x;
    if (blockIdx.z == 0) {
        int rel = blockIdx.y;
        const int* e = rel ? e_c : e_w;
        int E = rel ? Ec : Ew;
        int i = blockIdx.x * 256 + tid;
        if (i < E) atomicAdd(&g_deg[rel][e[E + i]], 1);
        return;
    }
    if (blockIdx.x >= 160) return;
    int b = blockIdx.y * 160 + blockIdx.x;
    if (b >= 320) return;
    int s = b >> 6;         // 0..4
    int i = b & 63;         // k-pair index
    int h = tid >> 7;       // 0/1: which row of the pair
    int j = tid & 127;      // output column n

    __shared__ float Arow[2][128];
    __shared__ float Crow[2][128];

    if (s == 0) {
        Crow[h][j] = wq_p[(size_t)(2 * i + h) * 128 + j];
    } else {
        const float* A; const float* B;
        switch (s) {
            case 1: A = wk_a; B = wrk_w; break;
            case 2: A = wv_a; B = wrv_w; break;
            case 3: A = wk_p; B = wrk_c; break;
            default:A = wv_p; B = wrv_c; break;
        }
        Arow[h][j] = A[(size_t)(2 * i + h) * 128 + j];
        __syncthreads();
        float acc = 0.f;
#pragma unroll 8
        for (int k = 0; k < 128; k++) acc += Arow[h][k] * B[(size_t)k * 128 + j];
        Crow[h][j] = acc;
    }
    __syncthreads();
    if (h == 0) {
        float c0 = Crow[0][j], c1 = Crow[1][j];
        float h0 = __bfloat162float(__float2bfloat16(c0));
        float h1 = __bfloat162float(__float2bfloat16(c1));
        uint2 w;
        w.x = pack_bf2(h0, h1);
        w.y = pack_bf2(c0 - h0, c1 - h1);
        g_wI[s][j * 64 + i] = w;
    }
}

// ---------------- launch 2: scan ------------------------------------------------
__global__ void scan_kernel(int n) {
    int rel = blockIdx.x;
    __shared__ int sm[1024];
    int tid = threadIdx.x;
    int C = (n + 1023) / 1024;
    int b = tid * C;
    int e = b + C; if (e > n) e = n;
    if (b > n) b = n;
    int s = 0;
    for (int i = b; i < e; i++) s += g_deg[rel][i];
    sm[tid] = s;
    __syncthreads();
#pragma unroll
    for (int ofs = 1; ofs < 1024; ofs <<= 1) {
        int t = (tid >= ofs) ? sm[tid - ofs] : 0;
        __syncthreads();
        sm[tid] += t;
        __syncthreads();
    }
    int run = sm[tid] - s;
    for (int i = b; i < e; i++) { int d = g_deg[rel][i]; g_off[rel][i] = run; run += d; }
    if (e == n) g_off[rel][n] = run;
}

// ---------------- launch 3: mma GEMM (z<5) + scatter (z=5) ---------------------
#define SMS 20

__global__ __launch_bounds__(256, 2) void fusedB_kernel(
    const float4* __restrict__ xa4, const float4* __restrict__ xp4, int nrows,
    const int* __restrict__ e_w, int Ew, const int* __restrict__ e_c, int Ec,
    int gb) {
    if (blockIdx.z == 5) {
        int rel = blockIdx.y;
        const int* e = rel ? e_c : e_w;
        int E = rel ? Ec : Ew;
        int i = blockIdx.x * 256 + threadIdx.x;
        if (i < E) {
            int src = e[i];
            int dst = e[E + i];
            int p = atomicAdd(&g_cur[rel][dst], 1);
            g_csr[rel][g_off[rel][dst] + p] = src;
        }
        return;
    }
    if (blockIdx.x >= gb) return;

    int slice = blockIdx.z;
    int chalf = blockIdx.y;
    const float4* Xf4 = (slice == 1 || slice == 2) ? xa4 : xp4;
    const uint2* WI = g_wI[slice];

    __shared__ uint2 AhL[128 * SMS];
    __shared__ uint2 BhL[64 * SMS];

    int tid = threadIdx.x;
    int lane = tid & 31;
    int warp = tid >> 5;
    int wm = warp & 3;
    int wn = warp >> 2;
    int row0 = blockIdx.x * 128;

    float acc[2][4][4];
#pragma unroll
    for (int mt = 0; mt < 2; mt++)
#pragma unroll
        for (int nt = 0; nt < 4; nt++)
#pragma unroll
            for (int r = 0; r < 4; r++) acc[mt][nt][r] = 0.f;

    int lq = lane >> 2;
    int lc = lane & 3;

    for (int ch = 0; ch < 4; ch++) {
#pragma unroll
        for (int it = 0; it < 4; it++) {
            int lin = it * 256 + tid;
            int r = lin >> 3, f4 = lin & 7;
            int gr = row0 + r;
            float4 x4 = make_float4(0.f, 0.f, 0.f, 0.f);
            if (gr < nrows) x4 = Xf4[(size_t)gr * 32 + ch * 8 + f4];
            float h0 = __bfloat162float(__float2bfloat16(x4.x));
            float h1 = __bfloat162float(__float2bfloat16(x4.y));
            float h2 = __bfloat162float(__float2bfloat16(x4.z));
            float h3 = __bfloat162float(__float2bfloat16(x4.w));
            uint4 o;
            o.x = pack_bf2(h0, h1);
            o.y = pack_bf2(x4.x - h0, x4.y - h1);
            o.z = pack_bf2(h2, h3);
            o.w = pack_bf2(x4.z - h2, x4.w - h3);
            *(uint4*)&AhL[r * SMS + f4 * 2] = o;
        }
#pragma unroll
        for (int it = 0; it < 2; it++) {
            int lin = it * 256 + tid;
            int r = lin >> 3, p = lin & 7;
            uint4 w = *(const uint4*)&WI[(size_t)(chalf * 64 + r) * 64 + ch * 16 + p * 2];
            *(uint4*)&BhL[r * SMS + p * 2] = w;
        }
        __syncthreads();

#pragma unroll
        for (int s = 0; s < 2; s++) {
            int kb = s * 8;
            uint32_t ah[2][4], al[2][4];
#pragma unroll
            for (int mt = 0; mt < 2; mt++) {
                int rbase = wm * 32 + mt * 16;
                int i0 = (rbase + lq) * SMS + kb + lc;
                int i1 = (rbase + lq + 8) * SMS + kb + lc;
                uint2 a0 = AhL[i0], a1 = AhL[i1];
                uint2 a2 = AhL[i0 + 4], a3 = AhL[i1 + 4];
                ah[mt][0] = a0.x; ah[mt][1] = a1.x; ah[mt][2] = a2.x; ah[mt][3] = a3.x;
                al[mt][0] = a0.y; al[mt][1] = a1.y; al[mt][2] = a2.y; al[mt][3] = a3.y;
            }
#pragma unroll
            for (int nt = 0; nt < 4; nt++) {
                int nb = (wn * 32 + nt * 8 + lq) * SMS + kb + lc;
                uint2 b0 = BhL[nb], b1 = BhL[nb + 4];
                uint32_t bh0 = b0.x, bl0 = b0.y, bh1 = b1.x, bl1 = b1.y;
#pragma unroll
                for (int mt = 0; mt < 2; mt++) {
                    float* d = acc[mt][nt];
                    asm volatile(
                        "mma.sync.aligned.m16n8k16.row.col.f32.bf16.bf16.f32 "
                        "{%0,%1,%2,%3}, {%4,%5,%6,%7}, {%8,%9}, {%0,%1,%2,%3};"
                        : "+f"(d[0]), "+f"(d[1]), "+f"(d[2]), "+f"(d[3])
                        : "r"(ah[mt][0]), "r"(ah[mt][1]), "r"(ah[mt][2]), "r"(ah[mt][3]),
                          "r"(bh0), "r"(bh1));
                    asm volatile(
                        "mma.sync.aligned.m16n8k16.row.col.f32.bf16.bf16.f32 "
                        "{%0,%1,%2,%3}, {%4,%5,%6,%7}, {%8,%9}, {%0,%1,%2,%3};"
                        : "+f"(d[0]), "+f"(d[1]), "+f"(d[2]), "+f"(d[3])
                        : "r"(ah[mt][0]), "r"(ah[mt][1]), "r"(ah[mt][2]), "r"(ah[mt][3]),
                          "r"(bl0), "r"(bl1));
                    asm volatile(
                        "mma.sync.aligned.m16n8k16.row.col.f32.bf16.bf16.f32 "
                        "{%0,%1,%2,%3}, {%4,%5,%6,%7}, {%8,%9}, {%0,%1,%2,%3};"
                        : "+f"(d[0]), "+f"(d[1]), "+f"(d[2]), "+f"(d[3])
                        : "r"(al[mt][0]), "r"(al[mt][1]), "r"(al[mt][2]), "r"(al[mt][3]),
                          "r"(bh0), "r"(bh1));
                }
            }
        }
        __syncthreads();
    }

    if (slice == 0) {
        float* Y = g_qp;
#pragma unroll
        for (int mt = 0; mt < 2; mt++)
#pragma unroll
            for (int nt = 0; nt < 4; nt++) {
                int col = chalf * 64 + wn * 32 + nt * 8 + lc * 2;
                int r0 = row0 + wm * 32 + mt * 16 + lq;
                if (r0 < nrows)
                    *(float2*)(Y + (size_t)r0 * 128 + col) =
                        make_float2(acc[mt][nt][0], acc[mt][nt][1]);
                int r1 = r0 + 8;
                if (r1 < nrows)
                    *(float2*)(Y + (size_t)r1 * 128 + col) =
                        make_float2(acc[mt][nt][2], acc[mt][nt][3]);
            }
    } else {
        __half* Y;
        switch (slice) {
            case 1: Y = g_rkh[0]; break;
            case 2: Y = g_rvh[0]; break;
            case 3: Y = g_rkh[1]; break;
            default:Y = g_rvh[1]; break;
        }
#pragma unroll
        for (int mt = 0; mt < 2; mt++)
#pragma unroll
            for (int nt = 0; nt < 4; nt++) {
                int col = chalf * 64 + wn * 32 + nt * 8 + lc * 2;
                int pos = col;
                int r0 = row0 + wm * 32 + mt * 16 + lq;
                if (r0 < nrows)
                    *(__half2*)(Y + (size_t)r0 * 128 + pos) =
                        __float22half2_rn(make_float2(acc[mt][nt][0], acc[mt][nt][1]));
                int r1 = r0 + 8;
                if (r1 < nrows)
                    *(__half2*)(Y + (size_t)r1 * 128 + pos) =
                        __float22half2_rn(make_float2(acc[mt][nt][2], acc[mt][nt][3]));
            }
    }
}

// ---------------- launch 4 (PROFILED SLOT): aggregation ------------------------
__device__ __forceinline__ float4 half4_to_float4(uint2 u) {
    __half2 h0 = *(__half2*)&u.x;
    __half2 h1 = *(__half2*)&u.y;
    float2 f0 = __half22float2(h0);
    float2 f1 = __half22float2(h1);
    return make_float4(f0.x, f0.y, f1.x, f1.y);
}

__device__ __forceinline__ float head_dot(float4 q4, float4 k4) {
    float p = q4.x*k4.x + q4.y*k4.y + q4.z*k4.z + q4.w*k4.w;
    p += __shfl_xor_sync(0xFFFFFFFFu, p, 1);
    p += __shfl_xor_sync(0xFFFFFFFFu, p, 2);
    p += __shfl_xor_sync(0xFFFFFFFFu, p, 4);
    return p;
}

__device__ __forceinline__ void rel_agg(
    const __half* __restrict__ rk, const __half* __restrict__ rv,
    const int* __restrict__ csr, int beg, int end,
    float4 q4, int lane, float4& acc, float& s) {
    const float scale = 0.17677669529663687f;   // 1/sqrt(32)
    float s0a = 0.f, s1a = 0.f;
    float4 A0 = make_float4(0.f,0.f,0.f,0.f);
    float4 A1 = make_float4(0.f,0.f,0.f,0.f);

    int e = beg;
    for (; e + 4 <= end; e += 4) {
        int i0 = csr[e], i1 = csr[e+1], i2 = csr[e+2], i3 = csr[e+3];
        float4 k0 = half4_to_float4(*(const uint2*)(rk + (size_t)i0 * 128 + lane * 4));
        float4 k1 = half4_to_float4(*(const uint2*)(rk + (size_t)i1 * 128 + lane * 4));
        float4 k2 = half4_to_float4(*(const uint2*)(rk + (size_t)i2 * 128 + lane * 4));
        float4 k3 = half4_to_float4(*(const uint2*)(rk + (size_t)i3 * 128 + lane * 4));
        float4 v0 = half4_to_float4(*(const uint2*)(rv + (size_t)i0 * 128 + lane * 4));
        float4 v1 = half4_to_float4(*(const uint2*)(rv + (size_t)i1 * 128 + lane * 4));
        float4 v2 = half4_to_float4(*(const uint2*)(rv + (size_t)i2 * 128 + lane * 4));
        float4 v3 = half4_to_float4(*(const uint2*)(rv + (size_t)i3 * 128 + lane * 4));
        float p0 = __expf(head_dot(q4, k0) * scale);
        float p1 = __expf(head_dot(q4, k1) * scale);
        float p2 = __expf(head_dot(q4, k2) * scale);
        float p3 = __expf(head_dot(q4, k3) * scale);
        s0a += p0 + p2;
        s1a += p1 + p3;
        A0.x += p0*v0.x + p2*v2.x;  A1.x += p1*v1.x + p3*v3.x;
        A0.y += p0*v0.y + p2*v2.y;  A1.y += p1*v1.y + p3*v3.y;
        A0.z += p0*v0.z + p2*v2.z;  A1.z += p1*v1.z + p3*v3.z;
        A0.w += p0*v0.w + p2*v2.w;  A1.w += p1*v1.w + p3*v3.w;
    }
    for (; e < end; e++) {
        int i0 = csr[e];
        float4 k0 = half4_to_float4(*(const uint2*)(rk + (size_t)i0 * 128 + lane * 4));
        float4 v0 = half4_to_float4(*(const uint2*)(rv + (size_t)i0 * 128 + lane * 4));
        float p0 = __expf(head_dot(q4, k0) * scale);
        s0a += p0;
        A0.x += p0*v0.x; A0.y += p0*v0.y; A0.z += p0*v0.z; A0.w += p0*v0.w;
    }
    s = s0a + s1a;
    acc = make_float4(A0.x + A1.x, A0.y + A1.y, A0.z + A1.z, A0.w + A1.w);
}

__global__ __launch_bounds__(256) void aggregate2_kernel(int n) {
    int warp = (blockIdx.x * blockDim.x + threadIdx.x) >> 5;
    if (warp >= n) return;
    int lane = threadIdx.x & 31;

    float4 q4 = *(const float4*)(g_qp + (size_t)warp * 128 + lane * 4);

    float4 aw, ac;
    float sw, sc;
    int bw = g_off[0][warp], ew = g_off[0][warp + 1];
    int bc = g_off[1][warp], ec = g_off[1][warp + 1];
    rel_agg(g_rkh[0], g_rvh[0], g_csr[0], bw, ew, q4, lane, aw, sw);
    rel_agg(g_rkh[1], g_rvh[1], g_csr[1], bc, ec, q4, lane, ac, sc);

    float iw = (ew > bw) ? 1.f / sw : 0.f;
    float ic = (ec > bc) ? 1.f / sc : 0.f;
    float4 o;
    o.x = aw.x * iw + ac.x * ic;
    o.y = aw.y * iw + ac.y * ic;
    o.z = aw.z * iw + ac.z * ic;
    o.w = aw.w * iw + ac.w * ic;
    *(float4*)(g_outp + (size_t)warp * 128 + lane * 4) = o;
}

// ---------------- launch 5: final projections + counter re-zero ----------------
__global__ __launch_bounds__(256) void final_kernel(
    const float* __restrict__ Xa, const float* __restrict__ Xp,
    const float* __restrict__ Wr_a, const float* __restrict__ Wo_p,
    const float* __restrict__ Wr_p, const float* __restrict__ bo_a,
    const float* __restrict__ bo_p, float* __restrict__ out, int n) {
    int type = blockIdx.y;
    if (type == 2) {
        int i = blockIdx.x * blockDim.x + threadIdx.x;
        if (i < n) {
            g_deg[0][i] = 0; g_deg[1][i] = 0;
            g_cur[0][i] = 0; g_cur[1][i] = 0;
        }
        return;
    }
    __shared__ float Ws[2 * 128 * 32];
    if (type == 0) {
        for (int i = threadIdx.x; i < 4096; i += blockDim.x) Ws[i] = Wr_a[i];
    } else {
        for (int i = threadIdx.x; i < 4096; i += blockDim.x) Ws[i] = Wo_p[i];
        for (int i = threadIdx.x; i < 4096; i += blockDim.x) Ws[4096 + i] = Wr_p[i];
    }
    __syncthreads();
    int warp = blockIdx.x * (blockDim.x >> 5) + (threadIdx.x >> 5);
    int lane = threadIdx.x & 31;
    if (warp >= n) return;

    if (type == 0) {
        const float4* xr4 = (const float4*)(Xa + (size_t)warp * 128);
        float a0 = 0.f, a1 = 0.f;
#pragma unroll
        for (int k4 = 0; k4 < 32; k4++) {
            float4 x4 = xr4[k4];
            a0 += x4.x * Ws[(k4*4+0)*32 + lane] + x4.y * Ws[(k4*4+1)*32 + lane];
            a1 += x4.z * Ws[(k4*4+2)*32 + lane] + x4.w * Ws[(k4*4+3)*32 + lane];
        }
        out[(size_t)warp * 32 + lane] = bo_a[lane] + a0 + a1;
    } else {
        const float4* op4 = (const float4*)(g_outp + (size_t)warp * 128);
        const float4* xr4 = (const float4*)(Xp + (size_t)warp * 128);
        float a0 = 0.f, a1 = 0.f;
#pragma unroll
        for (int k4 = 0; k4 < 32; k4++) {
            float4 x4 = op4[k4];
            a0 += x4.x * Ws[(k4*4+0)*32 + lane] + x4.y * Ws[(k4*4+1)*32 + lane];
            a1 += x4.z * Ws[(k4*4+2)*32 + lane] + x4.w * Ws[(k4*4+3)*32 + lane];
        }
#pragma unroll
        for (int k4 = 0; k4 < 32; k4++) {
            float4 x4 = xr4[k4];
            a0 += x4.x * Ws[4096 + (k4*4+0)*32 + lane] + x4.y * Ws[4096 + (k4*4+1)*32 + lane];
            a1 += x4.z * Ws[4096 + (k4*4+2)*32 + lane] + x4.w * Ws[4096 + (k4*4+3)*32 + lane];
        }
        out[(size_t)(n + warp) * 32 + lane] = bo_p[lane] + a0 + a1;
    }
}

// ---------------- launch --------------------------------------------------------
extern "C" void kernel_launch(void* const* d_in, const int* in_sizes, int n_in,
                              void* d_out, int out_size) {
    const float* x_a   = (const float*)d_in[0];
    const float* x_p   = (const float*)d_in[1];
    const int*   e_w   = (const int*)d_in[2];
    const int*   e_c   = (const int*)d_in[3];
    const float* wk_a  = (const float*)d_in[5];
    const float* wv_a  = (const float*)d_in[6];
    const float* wq_p  = (const float*)d_in[7];
    const float* wk_p  = (const float*)d_in[8];
    const float* wv_p  = (const float*)d_in[9];
    const float* wrk_w = (const float*)d_in[10];
    const float* wrv_w = (const float*)d_in[11];
    const float* wrk_c = (const float*)d_in[12];
    const float* wrv_c = (const float*)d_in[13];
    const float* bo_a  = (const float*)d_in[15];
    const float* wo_p  = (const float*)d_in[16];
    const float* bo_p  = (const float*)d_in[17];
    const float* wr_a  = (const float*)d_in[18];
    const float* wr_p  = (const float*)d_in[19];
    float* out = (float*)d_out;

    int n  = in_sizes[0] / 128;
    int Ew = in_sizes[2] / 2;
    int Ec = in_sizes[3] / 2;

    int geb = (((Ew > Ec) ? Ew : Ec) + 255) / 256;
    int gb  = (n + 127) / 128;
    int ga  = (n + 7) / 8;
    int gf  = (n + 7) / 8;

    // launch 1: hist + compose/convert
    fusedA_kernel<<<dim3(geb, 2, 2), 256>>>(e_w, Ew, e_c, Ec, wq_p,
                                            wk_a, wv_a, wk_p, wv_p,
                                            wrk_w, wrv_w, wrk_c, wrv_c);
    // launch 2: scan
    scan_kernel<<<2, 1024>>>(n);
    // launch 3: GEMMs + scatter
    fusedB_kernel<<<dim3(geb, 2, 6), 256>>>((const float4*)x_a, (const float4*)x_p,
                                            n, e_w, Ew, e_c, Ec, gb);
    // launch 4 (profiled): aggregation
    aggregate2_kernel<<<ga, 256>>>(n);
    // launch 5: final projections + counter re-zero
    final_kernel<<<dim3(gf, 3), 256>>>(x_a, x_p, wr_a, wo_p, wr_p,
                                       bo_a, bo_p, out, n);
}

// round 14
// speedup vs baseline: 1.0840x; 1.0438x over previous
#include <cuda_runtime.h>
#include <cuda_bf16.h>
#include <cuda_fp16.h>
#include <stdint.h>
#include <math.h>

#define NMAX 50048
#define EMAX 600064

// ---------------- scratch (static __device__ — no allocation) ----------------
__device__ float  g_qp [NMAX * 128];
__device__ __half g_rkh[2][NMAX * 128];
__device__ __half g_rvh[2][NMAX * 128];
__device__ float  g_outp[NMAX * 128];
__device__ float  g_cw[4][128 * 128];
__device__ uint2  g_wI[5][128 * 64];      // [n][k-pair] interleaved (hi, lo) bf16x2
__device__ int    g_deg[2][NMAX];
__device__ int    g_cur[2][NMAX];
__device__ int    g_off[2][NMAX + 1];
__device__ int    g_csr[2][EMAX];

// ---------------- compose weights + zero counters ------------------------------
__global__ void compose_kernel(const float* __restrict__ A0, const float* __restrict__ B0,
                               const float* __restrict__ A1, const float* __restrict__ B1,
                               const float* __restrict__ A2, const float* __restrict__ B2,
                               const float* __restrict__ A3, const float* __restrict__ B3,
                               int n) {
    int gid = (blockIdx.y * gridDim.x + blockIdx.x) * blockDim.x + threadIdx.x;
    if (gid < n) {
        g_deg[0][gid] = 0; g_deg[1][gid] = 0;
        g_cur[0][gid] = 0; g_cur[1][gid] = 0;
    }

    const float* A; const float* B;
    switch (blockIdx.y) {
        case 0: A = A0; B = B0; break;
        case 1: A = A1; B = B1; break;
        case 2: A = A2; B = B2; break;
        default: A = A3; B = B3; break;
    }
    float* C = g_cw[blockIdx.y];
    int i = blockIdx.x;
    int j = threadIdx.x;
    __shared__ float As[128];
    As[j] = A[i * 128 + j];
    __syncthreads();
    float acc = 0.f;
#pragma unroll 8
    for (int k = 0; k < 128; k++) acc += As[k] * B[k * 128 + j];
    C[i * 128 + j] = acc;
}

// ---------------- weight split: [k][n] f32 -> [n][k-pair] uint2 (hi,lo) --------
__device__ __forceinline__ uint32_t pack_bf2(float a, float b) {
    __nv_bfloat162 h = __floats2bfloat162_rn(a, b);
    return *(uint32_t*)&h;
}

__global__ void convert_w_kernel(const float* __restrict__ wq_p) {
    int s = blockIdx.y;
    const float* src = (s == 0) ? wq_p : g_cw[s - 1];
    int i = blockIdx.x * blockDim.x + threadIdx.x;   // 0..8191
    int nn = i >> 6, kp = i & 63;
    float v0 = src[(2 * kp) * 128 + nn];
    float v1 = src[(2 * kp + 1) * 128 + nn];
    float h0 = __bfloat162float(__float2bfloat16(v0));
    float h1 = __bfloat162float(__float2bfloat16(v1));
    uint2 w;
    w.x = pack_bf2(h0, h1);
    w.y = pack_bf2(v0 - h0, v1 - h1);
    g_wI[s][nn * 64 + kp] = w;
}

// ---------------- tensor-core GEMM (bf16x3), 5 products, double-buffered -------
// grid (ceil(n/128), 2, 5), 256 threads, warp tile 32x32.
// Dynamic smem: 2 stages x (A 128x SMS + B 64x SMS) uint2 = 61440 bytes.
#define SMS 20
#define STAGE_U2 (192 * SMS)     // uint2 per stage (A:128*SMS, B:64*SMS)

__global__ __launch_bounds__(256, 2) void mma_gemm5(
    const float4* __restrict__ xa4, const float4* __restrict__ xp4, int nrows) {
    extern __shared__ uint2 dynsm[];
    int slice = blockIdx.z;
    int chalf = blockIdx.y;
    const float4* Xf4 = (slice == 1 || slice == 2) ? xa4 : xp4;
    const uint2* WI = g_wI[slice];

    int tid = threadIdx.x;
    int lane = tid & 31;
    int warp = tid >> 5;
    int wm = warp & 3;
    int wn = warp >> 2;
    int row0 = blockIdx.x * 128;

    float acc[2][4][4];
#pragma unroll
    for (int mt = 0; mt < 2; mt++)
#pragma unroll
        for (int nt = 0; nt < 4; nt++)
#pragma unroll
            for (int r = 0; r < 4; r++) acc[mt][nt][r] = 0.f;

    int lq = lane >> 2;
    int lc = lane & 3;

    // staging lambda-ish: stage chunk ch into buffer buf
    auto stage = [&](int ch, uint2* A, uint2* B) {
#pragma unroll
        for (int it = 0; it < 4; it++) {
            int lin = it * 256 + tid;       // 0..1023
            int r = lin >> 3, f4 = lin & 7;
            int gr = row0 + r;
            float4 x4 = make_float4(0.f, 0.f, 0.f, 0.f);
            if (gr < nrows) x4 = Xf4[(size_t)gr * 32 + ch * 8 + f4];
            float h0 = __bfloat162float(__float2bfloat16(x4.x));
            float h1 = __bfloat162float(__float2bfloat16(x4.y));
            float h2 = __bfloat162float(__float2bfloat16(x4.z));
            float h3 = __bfloat162float(__float2bfloat16(x4.w));
            uint4 o;
            o.x = pack_bf2(h0, h1);
            o.y = pack_bf2(x4.x - h0, x4.y - h1);
            o.z = pack_bf2(h2, h3);
            o.w = pack_bf2(x4.z - h2, x4.w - h3);
            *(uint4*)&A[r * SMS + f4 * 2] = o;
        }
#pragma unroll
        for (int it = 0; it < 2; it++) {
            int lin = it * 256 + tid;       // 0..511
            int r = lin >> 3, p = lin & 7;
            uint4 w = *(const uint4*)&WI[(size_t)(chalf * 64 + r) * 64 + ch * 16 + p * 2];
            *(uint4*)&B[r * SMS + p * 2] = w;
        }
    };

    uint2* Abuf[2] = { dynsm,            dynsm + STAGE_U2 };
    uint2* Bbuf[2] = { dynsm + 128*SMS,  dynsm + STAGE_U2 + 128*SMS };

    stage(0, Abuf[0], Bbuf[0]);
    __syncthreads();

#pragma unroll
    for (int ch = 0; ch < 4; ch++) {
        int cur = ch & 1;
        if (ch < 3) stage(ch + 1, Abuf[cur ^ 1], Bbuf[cur ^ 1]);

        const uint2* AhL = Abuf[cur];
        const uint2* BhL = Bbuf[cur];
#pragma unroll
        for (int s = 0; s < 2; s++) {
            int kb = s * 8;
            uint32_t ah[2][4], al[2][4];
#pragma unroll
            for (int mt = 0; mt < 2; mt++) {
                int rbase = wm * 32 + mt * 16;
                int i0 = (rbase + lq) * SMS + kb + lc;
                int i1 = (rbase + lq + 8) * SMS + kb + lc;
                uint2 a0 = AhL[i0], a1 = AhL[i1];
                uint2 a2 = AhL[i0 + 4], a3 = AhL[i1 + 4];
                ah[mt][0] = a0.x; ah[mt][1] = a1.x; ah[mt][2] = a2.x; ah[mt][3] = a3.x;
                al[mt][0] = a0.y; al[mt][1] = a1.y; al[mt][2] = a2.y; al[mt][3] = a3.y;
            }
#pragma unroll
            for (int nt = 0; nt < 4; nt++) {
                int nb = (wn * 32 + nt * 8 + lq) * SMS + kb + lc;
                uint2 b0 = BhL[nb], b1 = BhL[nb + 4];
                uint32_t bh0 = b0.x, bl0 = b0.y, bh1 = b1.x, bl1 = b1.y;
#pragma unroll
                for (int mt = 0; mt < 2; mt++) {
                    float* d = acc[mt][nt];
                    asm volatile(
                        "mma.sync.aligned.m16n8k16.row.col.f32.bf16.bf16.f32 "
                        "{%0,%1,%2,%3}, {%4,%5,%6,%7}, {%8,%9}, {%0,%1,%2,%3};"
                        : "+f"(d[0]), "+f"(d[1]), "+f"(d[2]), "+f"(d[3])
                        : "r"(ah[mt][0]), "r"(ah[mt][1]), "r"(ah[mt][2]), "r"(ah[mt][3]),
                          "r"(bh0), "r"(bh1));
                    asm volatile(
                        "mma.sync.aligned.m16n8k16.row.col.f32.bf16.bf16.f32 "
                        "{%0,%1,%2,%3}, {%4,%5,%6,%7}, {%8,%9}, {%0,%1,%2,%3};"
                        : "+f"(d[0]), "+f"(d[1]), "+f"(d[2]), "+f"(d[3])
                        : "r"(ah[mt][0]), "r"(ah[mt][1]), "r"(ah[mt][2]), "r"(ah[mt][3]),
                          "r"(bl0), "r"(bl1));
                    asm volatile(
                        "mma.sync.aligned.m16n8k16.row.col.f32.bf16.bf16.f32 "
                        "{%0,%1,%2,%3}, {%4,%5,%6,%7}, {%8,%9}, {%0,%1,%2,%3};"
                        : "+f"(d[0]), "+f"(d[1]), "+f"(d[2]), "+f"(d[3])
                        : "r"(al[mt][0]), "r"(al[mt][1]), "r"(al[mt][2]), "r"(al[mt][3]),
                          "r"(bh0), "r"(bh1));
                }
            }
        }
        __syncthreads();
    }

    if (slice == 0) {
        float* Y = g_qp;
#pragma unroll
        for (int mt = 0; mt < 2; mt++)
#pragma unroll
            for (int nt = 0; nt < 4; nt++) {
                int col = chalf * 64 + wn * 32 + nt * 8 + lc * 2;
                int r0 = row0 + wm * 32 + mt * 16 + lq;
                if (r0 < nrows)
                    *(float2*)(Y + (size_t)r0 * 128 + col) =
                        make_float2(acc[mt][nt][0], acc[mt][nt][1]);
                int r1 = r0 + 8;
                if (r1 < nrows)
                    *(float2*)(Y + (size_t)r1 * 128 + col) =
                        make_float2(acc[mt][nt][2], acc[mt][nt][3]);
            }
    } else {
        __half* Y;
        switch (slice) {
            case 1: Y = g_rkh[0]; break;
            case 2: Y = g_rvh[0]; break;
            case 3: Y = g_rkh[1]; break;
            default:Y = g_rvh[1]; break;
        }
#pragma unroll
        for (int mt = 0; mt < 2; mt++)
#pragma unroll
            for (int nt = 0; nt < 4; nt++) {
                int col = chalf * 64 + wn * 32 + nt * 8 + lc * 2;
                int r0 = row0 + wm * 32 + mt * 16 + lq;
                if (r0 < nrows)
                    *(__half2*)(Y + (size_t)r0 * 128 + col) =
                        __float22half2_rn(make_float2(acc[mt][nt][0], acc[mt][nt][1]));
                int r1 = r0 + 8;
                if (r1 < nrows)
                    *(__half2*)(Y + (size_t)r1 * 128 + col) =
                        __float22half2_rn(make_float2(acc[mt][nt][2], acc[mt][nt][3]));
            }
    }
}

// ---------------- CSR build ----------------------------------------------------
__global__ void hist2_kernel(const int* __restrict__ e_w, int Ew,
                             const int* __restrict__ e_c, int Ec) {
    int rel = blockIdx.y;
    const int* e = rel ? e_c : e_w;
    int E = rel ? Ec : Ew;
    int i = blockIdx.x * blockDim.x + threadIdx.x;
    if (i < E) atomicAdd(&g_deg[rel][e[E + i]], 1);
}

__global__ void scan_kernel(int n) {
    int rel = blockIdx.x;
    __shared__ int sm[1024];
    int tid = threadIdx.x;
    int C = (n + 1023) / 1024;
    int b = tid * C;
    int e = b + C; if (e > n) e = n;
    if (b > n) b = n;
    int s = 0;
    for (int i = b; i < e; i++) s += g_deg[rel][i];
    sm[tid] = s;
    __syncthreads();
#pragma unroll
    for (int ofs = 1; ofs < 1024; ofs <<= 1) {
        int t = (tid >= ofs) ? sm[tid - ofs] : 0;
        __syncthreads();
        sm[tid] += t;
        __syncthreads();
    }
    int run = sm[tid] - s;
    for (int i = b; i < e; i++) { int d = g_deg[rel][i]; g_off[rel][i] = run; run += d; }
    if (e == n) g_off[rel][n] = run;
}

__global__ void scatter2_kernel(const int* __restrict__ e_w, int Ew,
                                const int* __restrict__ e_c, int Ec) {
    int rel = blockIdx.y;
    const int* e = rel ? e_c : e_w;
    int E = rel ? Ec : Ew;
    int i = blockIdx.x * blockDim.x + threadIdx.x;
    if (i < E) {
        int src = e[i];
        int dst = e[E + i];
        int p = atomicAdd(&g_cur[rel][dst], 1);
        g_csr[rel][g_off[rel][dst] + p] = src;
    }
}

// ---------------- per-destination MAX-FREE softmax aggregation -----------------
__device__ __forceinline__ float4 half4_to_float4(uint2 u) {
    __half2 h0 = *(__half2*)&u.x;
    __half2 h1 = *(__half2*)&u.y;
    float2 f0 = __half22float2(h0);
    float2 f1 = __half22float2(h1);
    return make_float4(f0.x, f0.y, f1.x, f1.y);
}

__device__ __forceinline__ float head_dot(float4 q4, float4 k4) {
    float p = q4.x*k4.x + q4.y*k4.y + q4.z*k4.z + q4.w*k4.w;
    p += __shfl_xor_sync(0xFFFFFFFFu, p, 1);
    p += __shfl_xor_sync(0xFFFFFFFFu, p, 2);
    p += __shfl_xor_sync(0xFFFFFFFFu, p, 4);
    return p;
}

__device__ __forceinline__ void rel_agg(
    const __half* __restrict__ rk, const __half* __restrict__ rv,
    const int* __restrict__ csr, int beg, int end,
    float4 q4, int lane, float4& acc, float& s) {
    const float scale = 0.17677669529663687f;   // 1/sqrt(32)
    float s0a = 0.f, s1a = 0.f;
    float4 A0 = make_float4(0.f,0.f,0.f,0.f);
    float4 A1 = make_float4(0.f,0.f,0.f,0.f);

    int e = beg;
    for (; e + 4 <= end; e += 4) {
        int i0 = csr[e], i1 = csr[e+1], i2 = csr[e+2], i3 = csr[e+3];
        float4 k0 = half4_to_float4(*(const uint2*)(rk + (size_t)i0 * 128 + lane * 4));
        float4 k1 = half4_to_float4(*(const uint2*)(rk + (size_t)i1 * 128 + lane * 4));
        float4 k2 = half4_to_float4(*(const uint2*)(rk + (size_t)i2 * 128 + lane * 4));
        float4 k3 = half4_to_float4(*(const uint2*)(rk + (size_t)i3 * 128 + lane * 4));
        float4 v0 = half4_to_float4(*(const uint2*)(rv + (size_t)i0 * 128 + lane * 4));
        float4 v1 = half4_to_float4(*(const uint2*)(rv + (size_t)i1 * 128 + lane * 4));
        float4 v2 = half4_to_float4(*(const uint2*)(rv + (size_t)i2 * 128 + lane * 4));
        float4 v3 = half4_to_float4(*(const uint2*)(rv + (size_t)i3 * 128 + lane * 4));
        float p0 = __expf(head_dot(q4, k0) * scale);
        float p1 = __expf(head_dot(q4, k1) * scale);
        float p2 = __expf(head_dot(q4, k2) * scale);
        float p3 = __expf(head_dot(q4, k3) * scale);
        s0a += p0 + p2;
        s1a += p1 + p3;
        A0.x += p0*v0.x + p2*v2.x;  A1.x += p1*v1.x + p3*v3.x;
        A0.y += p0*v0.y + p2*v2.y;  A1.y += p1*v1.y + p3*v3.y;
        A0.z += p0*v0.z + p2*v2.z;  A1.z += p1*v1.z + p3*v3.z;
        A0.w += p0*v0.w + p2*v2.w;  A1.w += p1*v1.w + p3*v3.w;
    }
    for (; e < end; e++) {
        int i0 = csr[e];
        float4 k0 = half4_to_float4(*(const uint2*)(rk + (size_t)i0 * 128 + lane * 4));
        float4 v0 = half4_to_float4(*(const uint2*)(rv + (size_t)i0 * 128 + lane * 4));
        float p0 = __expf(head_dot(q4, k0) * scale);
        s0a += p0;
        A0.x += p0*v0.x; A0.y += p0*v0.y; A0.z += p0*v0.z; A0.w += p0*v0.w;
    }
    s = s0a + s1a;
    acc = make_float4(A0.x + A1.x, A0.y + A1.y, A0.z + A1.z, A0.w + A1.w);
}

__global__ __launch_bounds__(256) void aggregate2_kernel(int n) {
    int warp = (blockIdx.x * blockDim.x + threadIdx.x) >> 5;
    if (warp >= n) return;
    int lane = threadIdx.x & 31;

    float4 q4 = *(const float4*)(g_qp + (size_t)warp * 128 + lane * 4);

    float4 aw, ac;
    float sw, sc;
    int bw = g_off[0][warp], ew = g_off[0][warp + 1];
    int bc = g_off[1][warp], ec = g_off[1][warp + 1];
    rel_agg(g_rkh[0], g_rvh[0], g_csr[0], bw, ew, q4, lane, aw, sw);
    rel_agg(g_rkh[1], g_rvh[1], g_csr[1], bc, ec, q4, lane, ac, sc);

    float iw = (ew > bw) ? 1.f / sw : 0.f;
    float ic = (ec > bc) ? 1.f / sc : 0.f;
    float4 o;
    o.x = aw.x * iw + ac.x * ic;
    o.y = aw.y * iw + ac.y * ic;
    o.z = aw.z * iw + ac.z * ic;
    o.w = aw.w * iw + ac.w * ic;
    *(float4*)(g_outp + (size_t)warp * 128 + lane * 4) = o;
}

// ---------------- final projections -------------------------------------------
__global__ __launch_bounds__(256) void final_kernel(
    const float* __restrict__ Xa, const float* __restrict__ Xp,
    const float* __restrict__ Wr_a, const float* __restrict__ Wo_p,
    const float* __restrict__ Wr_p, const float* __restrict__ bo_a,
    const float* __restrict__ bo_p, float* __restrict__ out, int n) {
    int type = blockIdx.y;
    __shared__ float Ws[2 * 128 * 32];
    if (type == 0) {
        for (int i = threadIdx.x; i < 4096; i += blockDim.x) Ws[i] = Wr_a[i];
    } else {
        for (int i = threadIdx.x; i < 4096; i += blockDim.x) Ws[i] = Wo_p[i];
        for (int i = threadIdx.x; i < 4096; i += blockDim.x) Ws[4096 + i] = Wr_p[i];
    }
    __syncthreads();
    int warp = blockIdx.x * (blockDim.x >> 5) + (threadIdx.x >> 5);
    int lane = threadIdx.x & 31;
    if (warp >= n) return;

    if (type == 0) {
        const float4* xr4 = (const float4*)(Xa + (size_t)warp * 128);
        float a0 = 0.f, a1 = 0.f;
#pragma unroll
        for (int k4 = 0; k4 < 32; k4++) {
            float4 x4 = xr4[k4];
            a0 += x4.x * Ws[(k4*4+0)*32 + lane] + x4.y * Ws[(k4*4+1)*32 + lane];
            a1 += x4.z * Ws[(k4*4+2)*32 + lane] + x4.w * Ws[(k4*4+3)*32 + lane];
        }
        out[(size_t)warp * 32 + lane] = bo_a[lane] + a0 + a1;
    } else {
        const float4* op4 = (const float4*)(g_outp + (size_t)warp * 128);
        const float4* xr4 = (const float4*)(Xp + (size_t)warp * 128);
        float a0 = 0.f, a1 = 0.f;
#pragma unroll
        for (int k4 = 0; k4 < 32; k4++) {
            float4 x4 = op4[k4];
            a0 += x4.x * Ws[(k4*4+0)*32 + lane] + x4.y * Ws[(k4*4+1)*32 + lane];
            a1 += x4.z * Ws[(k4*4+2)*32 + lane] + x4.w * Ws[(k4*4+3)*32 + lane];
        }
#pragma unroll
        for (int k4 = 0; k4 < 32; k4++) {
            float4 x4 = xr4[k4];
            a0 += x4.x * Ws[4096 + (k4*4+0)*32 + lane] + x4.y * Ws[4096 + (k4*4+1)*32 + lane];
            a1 += x4.z * Ws[4096 + (k4*4+2)*32 + lane] + x4.w * Ws[4096 + (k4*4+3)*32 + lane];
        }
        out[(size_t)(n + warp) * 32 + lane] = bo_p[lane] + a0 + a1;
    }
}

// ---------------- launch --------------------------------------------------------
extern "C" void kernel_launch(void* const* d_in, const int* in_sizes, int n_in,
                              void* d_out, int out_size) {
    const float* x_a   = (const float*)d_in[0];
    const float* x_p   = (const float*)d_in[1];
    const int*   e_w   = (const int*)d_in[2];
    const int*   e_c   = (const int*)d_in[3];
    const float* wk_a  = (const float*)d_in[5];
    const float* wv_a  = (const float*)d_in[6];
    const float* wq_p  = (const float*)d_in[7];
    const float* wk_p  = (const float*)d_in[8];
    const float* wv_p  = (const float*)d_in[9];
    const float* wrk_w = (const float*)d_in[10];
    const float* wrv_w = (const float*)d_in[11];
    const float* wrk_c = (const float*)d_in[12];
    const float* wrv_c = (const float*)d_in[13];
    const float* bo_a  = (const float*)d_in[15];
    const float* wo_p  = (const float*)d_in[16];
    const float* bo_p  = (const float*)d_in[17];
    const float* wr_a  = (const float*)d_in[18];
    const float* wr_p  = (const float*)d_in[19];
    float* out = (float*)d_out;

    int n  = in_sizes[0] / 128;
    int Ew = in_sizes[2] / 2;
    int Ec = in_sizes[3] / 2;

    const int DYN_SMEM = 2 * STAGE_U2 * (int)sizeof(uint2);   // 61440
    cudaFuncSetAttribute(mma_gemm5, cudaFuncAttributeMaxDynamicSharedMemorySize,
                         DYN_SMEM);

    // mma_gemm5 kept in the 4th launch slot (ncu capture)
    compose_kernel<<<dim3(128, 4), 128>>>(wk_a, wrk_w, wv_a, wrv_w,
                                          wk_p, wrk_c, wv_p, wrv_c, n);
    convert_w_kernel<<<dim3(32, 5), 256>>>(wq_p);
    int geb = (((Ew > Ec) ? Ew : Ec) + 255) / 256;
    hist2_kernel<<<dim3(geb, 2), 256>>>(e_w, Ew, e_c, Ec);

    int gb = (n + 127) / 128;
    mma_gemm5<<<dim3(gb, 2, 5), 256, DYN_SMEM>>>((const float4*)x_a,
                                                 (const float4*)x_p, n);

    scan_kernel<<<2, 1024>>>(n);
    scatter2_kernel<<<dim3(geb, 2), 256>>>(e_w, Ew, e_c, Ec);

    int ga = (n + 7) / 8;
    aggregate2_kernel<<<ga, 256>>>(n);

    int gf = (n + 7) / 8;
    final_kernel<<<dim3(gf, 2), 256>>>(x_a, x_p, wr_a, wo_p, wr_p,
                                       bo_a, bo_p, out, n);
}

// round 15
// speedup vs baseline: 1.1344x; 1.0465x over previous
#include <cuda_runtime.h>
#include <cuda_bf16.h>
#include <cuda_fp16.h>
#include <stdint.h>
#include <math.h>

#define NMAX 50048
#define EMAX 600064

// ---------------- scratch (static __device__ — no allocation) ----------------
__device__ float  g_qp [NMAX * 128];
__device__ __half g_rkh[2][NMAX * 128];
__device__ __half g_rvh[2][NMAX * 128];
__device__ float  g_outp[NMAX * 128];
__device__ float  g_cw[4][128 * 128];
__device__ uint2  g_wI[5][128 * 64];      // [n][k-pair] interleaved (hi, lo) bf16x2
__device__ int    g_deg[2][NMAX];
__device__ int    g_cur[2][NMAX];
__device__ int    g_off[2][NMAX + 1];
__device__ int    g_csr[2][EMAX];

// ---------------- compose weights + zero counters ------------------------------
__global__ void compose_kernel(const float* __restrict__ A0, const float* __restrict__ B0,
                               const float* __restrict__ A1, const float* __restrict__ B1,
                               const float* __restrict__ A2, const float* __restrict__ B2,
                               const float* __restrict__ A3, const float* __restrict__ B3,
                               int n) {
    int gid = (blockIdx.y * gridDim.x + blockIdx.x) * blockDim.x + threadIdx.x;
    if (gid < n) {
        g_deg[0][gid] = 0; g_deg[1][gid] = 0;
        g_cur[0][gid] = 0; g_cur[1][gid] = 0;
    }

    const float* A; const float* B;
    switch (blockIdx.y) {
        case 0: A = A0; B = B0; break;
        case 1: A = A1; B = B1; break;
        case 2: A = A2; B = B2; break;
        default: A = A3; B = B3; break;
    }
    float* C = g_cw[blockIdx.y];
    int i = blockIdx.x;
    int j = threadIdx.x;
    __shared__ float As[128];
    As[j] = A[i * 128 + j];
    __syncthreads();
    float acc = 0.f;
#pragma unroll 8
    for (int k = 0; k < 128; k++) acc += As[k] * B[k * 128 + j];
    C[i * 128 + j] = acc;
}

// ---------------- weight split: [k][n] f32 -> [n][k-pair] uint2 (hi,lo) --------
__device__ __forceinline__ uint32_t pack_bf2(float a, float b) {
    __nv_bfloat162 h = __floats2bfloat162_rn(a, b);
    return *(uint32_t*)&h;
}

__global__ void convert_w_kernel(const float* __restrict__ wq_p) {
    int s = blockIdx.y;
    const float* src = (s == 0) ? wq_p : g_cw[s - 1];
    int i = blockIdx.x * blockDim.x + threadIdx.x;   // 0..8191
    int nn = i >> 6, kp = i & 63;
    float v0 = src[(2 * kp) * 128 + nn];
    float v1 = src[(2 * kp + 1) * 128 + nn];
    float h0 = __bfloat162float(__float2bfloat16(v0));
    float h1 = __bfloat162float(__float2bfloat16(v1));
    uint2 w;
    w.x = pack_bf2(h0, h1);
    w.y = pack_bf2(v0 - h0, v1 - h1);
    g_wI[s][nn * 64 + kp] = w;
}

// ---------------- tensor-core GEMM (bf16x3), ldmatrix fragments ----------------
// grid (ceil(n/128), 2, 5), 256 threads, warp tile 32x32, double-buffered.
// Smem word layout per stage (uint32, stride 20 words/row):
//   Ah @ 0      (128 rows)   Al @ 2560
//   Bh @ 5120   (64 rows)    Bl @ 6400
// stage stride 7680 words; total 2*7680*4 = 61440 bytes.
#define SMS 20
#define AH_W 0
#define AL_W 2560
#define BH_W 5120
#define BL_W 6400
#define STG_W 7680

__device__ __forceinline__ void ldsm_x4(uint32_t addr, uint32_t* r) {
    asm volatile("ldmatrix.sync.aligned.m8n8.x4.shared.b16 {%0,%1,%2,%3}, [%4];"
        : "=r"(r[0]), "=r"(r[1]), "=r"(r[2]), "=r"(r[3]) : "r"(addr));
}

__global__ __launch_bounds__(256, 2) void mma_gemm5(
    const float4* __restrict__ xa4, const float4* __restrict__ xp4, int nrows) {
    extern __shared__ uint32_t dynsm[];
    int slice = blockIdx.z;
    int chalf = blockIdx.y;
    const float4* Xf4 = (slice == 1 || slice == 2) ? xa4 : xp4;
    const uint2* WI = g_wI[slice];

    int tid = threadIdx.x;
    int lane = tid & 31;
    int warp = tid >> 5;
    int wm = warp & 3;
    int wn = warp >> 2;
    int row0 = blockIdx.x * 128;

    float acc[2][4][4];
#pragma unroll
    for (int mt = 0; mt < 2; mt++)
#pragma unroll
        for (int nt = 0; nt < 4; nt++)
#pragma unroll
            for (int r = 0; r < 4; r++) acc[mt][nt][r] = 0.f;

    int lq = lane >> 2;
    int lc = lane & 3;

    // per-lane ldmatrix address offsets (bytes, within the Ah/Bh planes)
    int lrow = lane & 7, lsel = lane >> 3;          // matrix select 0..3
    uint32_t aoff = (uint32_t)(((lrow + (lsel & 1) * 8) * SMS + (lsel >> 1) * 4) * 4);
    uint32_t boff = (uint32_t)((((lsel >> 1) * 8 + lrow) * SMS) * 4 + (lsel & 1) * 16);

    uint32_t sbase = (uint32_t)__cvta_generic_to_shared(dynsm);

    auto stage = [&](int ch, int stW) {
#pragma unroll
        for (int it = 0; it < 4; it++) {
            int lin = it * 256 + tid;       // 0..1023
            int r = lin >> 3, f4 = lin & 7;
            int gr = row0 + r;
            float4 x4 = make_float4(0.f, 0.f, 0.f, 0.f);
            if (gr < nrows) x4 = Xf4[(size_t)gr * 32 + ch * 8 + f4];
            float h0 = __bfloat162float(__float2bfloat16(x4.x));
            float h1 = __bfloat162float(__float2bfloat16(x4.y));
            float h2 = __bfloat162float(__float2bfloat16(x4.z));
            float h3 = __bfloat162float(__float2bfloat16(x4.w));
            *(uint2*)&dynsm[stW + AH_W + r * SMS + f4 * 2] =
                make_uint2(pack_bf2(h0, h1), pack_bf2(h2, h3));
            *(uint2*)&dynsm[stW + AL_W + r * SMS + f4 * 2] =
                make_uint2(pack_bf2(x4.x - h0, x4.y - h1), pack_bf2(x4.z - h2, x4.w - h3));
        }
#pragma unroll
        for (int it = 0; it < 2; it++) {
            int lin = it * 256 + tid;       // 0..511
            int r = lin >> 3, p = lin & 7;
            uint4 w = *(const uint4*)&WI[(size_t)(chalf * 64 + r) * 64 + ch * 16 + p * 2];
            *(uint2*)&dynsm[stW + BH_W + r * SMS + p * 2] = make_uint2(w.x, w.z);
            *(uint2*)&dynsm[stW + BL_W + r * SMS + p * 2] = make_uint2(w.y, w.w);
        }
    };

    stage(0, 0);
    __syncthreads();

#pragma unroll
    for (int ch = 0; ch < 4; ch++) {
        int cur = ch & 1;
        if (ch < 3) stage(ch + 1, (cur ^ 1) * STG_W);

        uint32_t stB = sbase + (uint32_t)(cur * STG_W * 4);
#pragma unroll
        for (int s = 0; s < 2; s++) {
            uint32_t kB = (uint32_t)(s * 32);      // kb*4 bytes (kb = s*8 words)
            uint32_t ah[2][4], al[2][4];
#pragma unroll
            for (int mt = 0; mt < 2; mt++) {
                uint32_t rB = (uint32_t)((wm * 32 + mt * 16) * SMS * 4);
                ldsm_x4(stB + AH_W * 4 + rB + kB + aoff, ah[mt]);
                ldsm_x4(stB + AL_W * 4 + rB + kB + aoff, al[mt]);
            }
#pragma unroll
            for (int ntp = 0; ntp < 2; ntp++) {
                uint32_t nB = (uint32_t)((wn * 32 + ntp * 16) * SMS * 4);
                uint32_t bh2[4], bl2[4];
                ldsm_x4(stB + BH_W * 4 + nB + kB + boff, bh2);
                ldsm_x4(stB + BL_W * 4 + nB + kB + boff, bl2);
#pragma unroll
                for (int half = 0; half < 2; half++) {
                    int nt = ntp * 2 + half;
                    uint32_t bh0 = bh2[2 * half], bh1 = bh2[2 * half + 1];
                    uint32_t bl0 = bl2[2 * half], bl1 = bl2[2 * half + 1];
#pragma unroll
                    for (int mt = 0; mt < 2; mt++) {
                        float* d = acc[mt][nt];
                        asm volatile(
                            "mma.sync.aligned.m16n8k16.row.col.f32.bf16.bf16.f32 "
                            "{%0,%1,%2,%3}, {%4,%5,%6,%7}, {%8,%9}, {%0,%1,%2,%3};"
                            : "+f"(d[0]), "+f"(d[1]), "+f"(d[2]), "+f"(d[3])
                            : "r"(ah[mt][0]), "r"(ah[mt][1]), "r"(ah[mt][2]), "r"(ah[mt][3]),
                              "r"(bh0), "r"(bh1));
                        asm volatile(
                            "mma.sync.aligned.m16n8k16.row.col.f32.bf16.bf16.f32 "
                            "{%0,%1,%2,%3}, {%4,%5,%6,%7}, {%8,%9}, {%0,%1,%2,%3};"
                            : "+f"(d[0]), "+f"(d[1]), "+f"(d[2]), "+f"(d[3])
                            : "r"(ah[mt][0]), "r"(ah[mt][1]), "r"(ah[mt][2]), "r"(ah[mt][3]),
                              "r"(bl0), "r"(bl1));
                        asm volatile(
                            "mma.sync.aligned.m16n8k16.row.col.f32.bf16.bf16.f32 "
                            "{%0,%1,%2,%3}, {%4,%5,%6,%7}, {%8,%9}, {%0,%1,%2,%3};"
                            : "+f"(d[0]), "+f"(d[1]), "+f"(d[2]), "+f"(d[3])
                            : "r"(al[mt][0]), "r"(al[mt][1]), "r"(al[mt][2]), "r"(al[mt][3]),
                              "r"(bh0), "r"(bh1));
                    }
                }
            }
        }
        __syncthreads();
    }

    if (slice == 0) {
        float* Y = g_qp;
#pragma unroll
        for (int mt = 0; mt < 2; mt++)
#pragma unroll
            for (int nt = 0; nt < 4; nt++) {
                int col = chalf * 64 + wn * 32 + nt * 8 + lc * 2;
                int r0 = row0 + wm * 32 + mt * 16 + lq;
                if (r0 < nrows)
                    *(float2*)(Y + (size_t)r0 * 128 + col) =
                        make_float2(acc[mt][nt][0], acc[mt][nt][1]);
                int r1 = r0 + 8;
                if (r1 < nrows)
                    *(float2*)(Y + (size_t)r1 * 128 + col) =
                        make_float2(acc[mt][nt][2], acc[mt][nt][3]);
            }
    } else {
        __half* Y;
        switch (slice) {
            case 1: Y = g_rkh[0]; break;
            case 2: Y = g_rvh[0]; break;
            case 3: Y = g_rkh[1]; break;
            default:Y = g_rvh[1]; break;
        }
#pragma unroll
        for (int mt = 0; mt < 2; mt++)
#pragma unroll
            for (int nt = 0; nt < 4; nt++) {
                int col = chalf * 64 + wn * 32 + nt * 8 + lc * 2;
                int r0 = row0 + wm * 32 + mt * 16 + lq;
                if (r0 < nrows)
                    *(__half2*)(Y + (size_t)r0 * 128 + col) =
                        __float22half2_rn(make_float2(acc[mt][nt][0], acc[mt][nt][1]));
                int r1 = r0 + 8;
                if (r1 < nrows)
                    *(__half2*)(Y + (size_t)r1 * 128 + col) =
                        __float22half2_rn(make_float2(acc[mt][nt][2], acc[mt][nt][3]));
            }
    }
}

// ---------------- CSR build ----------------------------------------------------
__global__ void hist2_kernel(const int* __restrict__ e_w, int Ew,
                             const int* __restrict__ e_c, int Ec) {
    int rel = blockIdx.y;
    const int* e = rel ? e_c : e_w;
    int E = rel ? Ec : Ew;
    int i = blockIdx.x * blockDim.x + threadIdx.x;
    if (i < E) atomicAdd(&g_deg[rel][e[E + i]], 1);
}

__global__ void scan_kernel(int n) {
    int rel = blockIdx.x;
    __shared__ int sm[1024];
    int tid = threadIdx.x;
    int C = (n + 1023) / 1024;
    int b = tid * C;
    int e = b + C; if (e > n) e = n;
    if (b > n) b = n;
    int s = 0;
    for (int i = b; i < e; i++) s += g_deg[rel][i];
    sm[tid] = s;
    __syncthreads();
#pragma unroll
    for (int ofs = 1; ofs < 1024; ofs <<= 1) {
        int t = (tid >= ofs) ? sm[tid - ofs] : 0;
        __syncthreads();
        sm[tid] += t;
        __syncthreads();
    }
    int run = sm[tid] - s;
    for (int i = b; i < e; i++) { int d = g_deg[rel][i]; g_off[rel][i] = run; run += d; }
    if (e == n) g_off[rel][n] = run;
}

__global__ void scatter2_kernel(const int* __restrict__ e_w, int Ew,
                                const int* __restrict__ e_c, int Ec) {
    int rel = blockIdx.y;
    const int* e = rel ? e_c : e_w;
    int E = rel ? Ec : Ew;
    int i = blockIdx.x * blockDim.x + threadIdx.x;
    if (i < E) {
        int src = e[i];
        int dst = e[E + i];
        int p = atomicAdd(&g_cur[rel][dst], 1);
        g_csr[rel][g_off[rel][dst] + p] = src;
    }
}

// ---------------- per-destination MAX-FREE softmax aggregation -----------------
__device__ __forceinline__ float4 half4_to_float4(uint2 u) {
    __half2 h0 = *(__half2*)&u.x;
    __half2 h1 = *(__half2*)&u.y;
    float2 f0 = __half22float2(h0);
    float2 f1 = __half22float2(h1);
    return make_float4(f0.x, f0.y, f1.x, f1.y);
}

__device__ __forceinline__ float head_dot(float4 q4, float4 k4) {
    float p = q4.x*k4.x + q4.y*k4.y + q4.z*k4.z + q4.w*k4.w;
    p += __shfl_xor_sync(0xFFFFFFFFu, p, 1);
    p += __shfl_xor_sync(0xFFFFFFFFu, p, 2);
    p += __shfl_xor_sync(0xFFFFFFFFu, p, 4);
    return p;
}

__device__ __forceinline__ void rel_agg(
    const __half* __restrict__ rk, const __half* __restrict__ rv,
    const int* __restrict__ csr, int beg, int end,
    float4 q4, int lane, float4& acc, float& s) {
    const float scale = 0.17677669529663687f;   // 1/sqrt(32)
    float s0a = 0.f, s1a = 0.f;
    float4 A0 = make_float4(0.f,0.f,0.f,0.f);
    float4 A1 = make_float4(0.f,0.f,0.f,0.f);

    int e = beg;
    for (; e + 4 <= end; e += 4) {
        int i0 = csr[e], i1 = csr[e+1], i2 = csr[e+2], i3 = csr[e+3];
        float4 k0 = half4_to_float4(*(const uint2*)(rk + (size_t)i0 * 128 + lane * 4));
        float4 k1 = half4_to_float4(*(const uint2*)(rk + (size_t)i1 * 128 + lane * 4));
        float4 k2 = half4_to_float4(*(const uint2*)(rk + (size_t)i2 * 128 + lane * 4));
        float4 k3 = half4_to_float4(*(const uint2*)(rk + (size_t)i3 * 128 + lane * 4));
        float4 v0 = half4_to_float4(*(const uint2*)(rv + (size_t)i0 * 128 + lane * 4));
        float4 v1 = half4_to_float4(*(const uint2*)(rv + (size_t)i1 * 128 + lane * 4));
        float4 v2 = half4_to_float4(*(const uint2*)(rv + (size_t)i2 * 128 + lane * 4));
        float4 v3 = half4_to_float4(*(const uint2*)(rv + (size_t)i3 * 128 + lane * 4));
        float p0 = __expf(head_dot(q4, k0) * scale);
        float p1 = __expf(head_dot(q4, k1) * scale);
        float p2 = __expf(head_dot(q4, k2) * scale);
        float p3 = __expf(head_dot(q4, k3) * scale);
        s0a += p0 + p2;
        s1a += p1 + p3;
        A0.x += p0*v0.x + p2*v2.x;  A1.x += p1*v1.x + p3*v3.x;
        A0.y += p0*v0.y + p2*v2.y;  A1.y += p1*v1.y + p3*v3.y;
        A0.z += p0*v0.z + p2*v2.z;  A1.z += p1*v1.z + p3*v3.z;
        A0.w += p0*v0.w + p2*v2.w;  A1.w += p1*v1.w + p3*v3.w;
    }
    for (; e < end; e++) {
        int i0 = csr[e];
        float4 k0 = half4_to_float4(*(const uint2*)(rk + (size_t)i0 * 128 + lane * 4));
        float4 v0 = half4_to_float4(*(const uint2*)(rv + (size_t)i0 * 128 + lane * 4));
        float p0 = __expf(head_dot(q4, k0) * scale);
        s0a += p0;
        A0.x += p0*v0.x; A0.y += p0*v0.y; A0.z += p0*v0.z; A0.w += p0*v0.w;
    }
    s = s0a + s1a;
    acc = make_float4(A0.x + A1.x, A0.y + A1.y, A0.z + A1.z, A0.w + A1.w);
}

__global__ __launch_bounds__(256) void aggregate2_kernel(int n) {
    int warp = (blockIdx.x * blockDim.x + threadIdx.x) >> 5;
    if (warp >= n) return;
    int lane = threadIdx.x & 31;

    float4 q4 = *(const float4*)(g_qp + (size_t)warp * 128 + lane * 4);

    float4 aw, ac;
    float sw, sc;
    int bw = g_off[0][warp], ew = g_off[0][warp + 1];
    int bc = g_off[1][warp], ec = g_off[1][warp + 1];
    rel_agg(g_rkh[0], g_rvh[0], g_csr[0], bw, ew, q4, lane, aw, sw);
    rel_agg(g_rkh[1], g_rvh[1], g_csr[1], bc, ec, q4, lane, ac, sc);

    float iw = (ew > bw) ? 1.f / sw : 0.f;
    float ic = (ec > bc) ? 1.f / sc : 0.f;
    float4 o;
    o.x = aw.x * iw + ac.x * ic;
    o.y = aw.y * iw + ac.y * ic;
    o.z = aw.z * iw + ac.z * ic;
    o.w = aw.w * iw + ac.w * ic;
    *(float4*)(g_outp + (size_t)warp * 128 + lane * 4) = o;
}

// ---------------- final projections -------------------------------------------
__global__ __launch_bounds__(256) void final_kernel(
    const float* __restrict__ Xa, const float* __restrict__ Xp,
    const float* __restrict__ Wr_a, const float* __restrict__ Wo_p,
    const float* __restrict__ Wr_p, const float* __restrict__ bo_a,
    const float* __restrict__ bo_p, float* __restrict__ out, int n) {
    int type = blockIdx.y;
    __shared__ float Ws[2 * 128 * 32];
    if (type == 0) {
        for (int i = threadIdx.x; i < 4096; i += blockDim.x) Ws[i] = Wr_a[i];
    } else {
        for (int i = threadIdx.x; i < 4096; i += blockDim.x) Ws[i] = Wo_p[i];
        for (int i = threadIdx.x; i < 4096; i += blockDim.x) Ws[4096 + i] = Wr_p[i];
    }
    __syncthreads();
    int warp = blockIdx.x * (blockDim.x >> 5) + (threadIdx.x >> 5);
    int lane = threadIdx.x & 31;
    if (warp >= n) return;

    if (type == 0) {
        const float4* xr4 = (const float4*)(Xa + (size_t)warp * 128);
        float a0 = 0.f, a1 = 0.f;
#pragma unroll
        for (int k4 = 0; k4 < 32; k4++) {
            float4 x4 = xr4[k4];
            a0 += x4.x * Ws[(k4*4+0)*32 + lane] + x4.y * Ws[(k4*4+1)*32 + lane];
            a1 += x4.z * Ws[(k4*4+2)*32 + lane] + x4.w * Ws[(k4*4+3)*32 + lane];
        }
        out[(size_t)warp * 32 + lane] = bo_a[lane] + a0 + a1;
    } else {
        const float4* op4 = (const float4*)(g_outp + (size_t)warp * 128);
        const float4* xr4 = (const float4*)(Xp + (size_t)warp * 128);
        float a0 = 0.f, a1 = 0.f;
#pragma unroll
        for (int k4 = 0; k4 < 32; k4++) {
            float4 x4 = op4[k4];
            a0 += x4.x * Ws[(k4*4+0)*32 + lane] + x4.y * Ws[(k4*4+1)*32 + lane];
            a1 += x4.z * Ws[(k4*4+2)*32 + lane] + x4.w * Ws[(k4*4+3)*32 + lane];
        }
#pragma unroll
        for (int k4 = 0; k4 < 32; k4++) {
            float4 x4 = xr4[k4];
            a0 += x4.x * Ws[4096 + (k4*4+0)*32 + lane] + x4.y * Ws[4096 + (k4*4+1)*32 + lane];
            a1 += x4.z * Ws[4096 + (k4*4+2)*32 + lane] + x4.w * Ws[4096 + (k4*4+3)*32 + lane];
        }
        out[(size_t)(n + warp) * 32 + lane] = bo_p[lane] + a0 + a1;
    }
}

// ---------------- launch --------------------------------------------------------
extern "C" void kernel_launch(void* const* d_in, const int* in_sizes, int n_in,
                              void* d_out, int out_size) {
    const float* x_a   = (const float*)d_in[0];
    const float* x_p   = (const float*)d_in[1];
    const int*   e_w   = (const int*)d_in[2];
    const int*   e_c   = (const int*)d_in[3];
    const float* wk_a  = (const float*)d_in[5];
    const float* wv_a  = (const float*)d_in[6];
    const float* wq_p  = (const float*)d_in[7];
    const float* wk_p  = (const float*)d_in[8];
    const float* wv_p  = (const float*)d_in[9];
    const float* wrk_w = (const float*)d_in[10];
    const float* wrv_w = (const float*)d_in[11];
    const float* wrk_c = (const float*)d_in[12];
    const float* wrv_c = (const float*)d_in[13];
    const float* bo_a  = (const float*)d_in[15];
    const float* wo_p  = (const float*)d_in[16];
    const float* bo_p  = (const float*)d_in[17];
    const float* wr_a  = (const float*)d_in[18];
    const float* wr_p  = (const float*)d_in[19];
    float* out = (float*)d_out;

    int n  = in_sizes[0] / 128;
    int Ew = in_sizes[2] / 2;
    int Ec = in_sizes[3] / 2;

    const int DYN_SMEM = 2 * STG_W * 4;   // 61440 bytes
    cudaFuncSetAttribute(mma_gemm5, cudaFuncAttributeMaxDynamicSharedMemorySize,
                         DYN_SMEM);

    // mma_gemm5 kept in the 4th launch slot (ncu capture)
    compose_kernel<<<dim3(128, 4), 128>>>(wk_a, wrk_w, wv_a, wrv_w,
                                          wk_p, wrk_c, wv_p, wrv_c, n);
    convert_w_kernel<<<dim3(32, 5), 256>>>(wq_p);
    int geb = (((Ew > Ec) ? Ew : Ec) + 255) / 256;
    hist2_kernel<<<dim3(geb, 2), 256>>>(e_w, Ew, e_c, Ec);

    int gb = (n + 127) / 128;
    mma_gemm5<<<dim3(gb, 2, 5), 256, DYN_SMEM>>>((const float4*)x_a,
                                                 (const float4*)x_p, n);

    scan_kernel<<<2, 1024>>>(n);
    scatter2_kernel<<<dim3(geb, 2), 256>>>(e_w, Ew, e_c, Ec);

    int ga = (n + 7) / 8;
    aggregate2_kernel<<<ga, 256>>>(n);

    int gf = (n + 7) / 8;
    final_kernel<<<dim3(gf, 2), 256>>>(x_a, x_p, wr_a, wo_p, wr_p,
                                       bo_a, bo_p, out, n);
}

// round 16
// speedup vs baseline: 1.1444x; 1.0088x over previous
#include <cuda_runtime.h>
#include <cuda_bf16.h>
#include <cuda_fp16.h>
#include <stdint.h>
#include <math.h>

#define NMAX 50048
#define EMAX 600064

// ---------------- scratch (static __device__ — no allocation) ----------------
// g_deg/g_cur start zero (.bss) and are re-zeroed at the END of every call
// (final_kernel y==2 plane) so each call/graph replay sees zeros.
__device__ float  g_qp [NMAX * 128];
__device__ __half g_rkh[2][NMAX * 128];
__device__ __half g_rvh[2][NMAX * 128];
__device__ float  g_outp[NMAX * 128];
__device__ uint2  g_wI[5][128 * 64];      // [n][k-pair] interleaved (hi, lo) bf16x2
__device__ int    g_deg[2][NMAX];
__device__ int    g_cur[2][NMAX];
__device__ int    g_off[2][NMAX + 1];
__device__ int    g_csr[2][EMAX];

__device__ __forceinline__ uint32_t pack_bf2(float a, float b) {
    __nv_bfloat162 h = __floats2bfloat162_rn(a, b);
    return *(uint32_t*)&h;
}

// ---------------- launch 1: hist (z=0) + compose & weight-split (z=1) ----------
__global__ __launch_bounds__(256) void fusedA_kernel(
    const int* __restrict__ e_w, int Ew, const int* __restrict__ e_c, int Ec,
    const float* __restrict__ wq_p,
    const float* __restrict__ wk_a, const float* __restrict__ wv_a,
    const float* __restrict__ wk_p, const float* __restrict__ wv_p,
    const float* __restrict__ wrk_w, const float* __restrict__ wrv_w,
    const float* __restrict__ wrk_c, const float* __restrict__ wrv_c) {
    int tid = threadIdx.x;
    if (blockIdx.z == 0) {
        int rel = blockIdx.y;
        const int* e = rel ? e_c : e_w;
        int E = rel ? Ec : Ew;
        int i = blockIdx.x * 256 + tid;
        if (i < E) atomicAdd(&g_deg[rel][e[E + i]], 1);
        return;
    }
    if (blockIdx.x >= 160) return;
    int b = blockIdx.y * 160 + blockIdx.x;
    if (b >= 320) return;
    int s = b >> 6;         // slice 0..4
    int i = b & 63;         // k-pair index
    int h = tid >> 7;       // 0/1: which row of the pair
    int j = tid & 127;      // output column n

    __shared__ float Arow[2][128];
    __shared__ float Crow[2][128];

    if (s == 0) {
        Crow[h][j] = wq_p[(size_t)(2 * i + h) * 128 + j];
    } else {
        const float* A; const float* B;
        switch (s) {
            case 1: A = wk_a; B = wrk_w; break;
            case 2: A = wv_a; B = wrv_w; break;
            case 3: A = wk_p; B = wrk_c; break;
            default:A = wv_p; B = wrv_c; break;
        }
        Arow[h][j] = A[(size_t)(2 * i + h) * 128 + j];
        __syncthreads();
        float acc = 0.f;
#pragma unroll 8
        for (int k = 0; k < 128; k++) acc += Arow[h][k] * B[(size_t)k * 128 + j];
        Crow[h][j] = acc;
    }
    __syncthreads();
    if (h == 0) {
        float c0 = Crow[0][j], c1 = Crow[1][j];
        float h0 = __bfloat162float(__float2bfloat16(c0));
        float h1 = __bfloat162float(__float2bfloat16(c1));
        uint2 w;
        w.x = pack_bf2(h0, h1);
        w.y = pack_bf2(c0 - h0, c1 - h1);
        g_wI[s][j * 64 + i] = w;
    }
}

// ---------------- launch 2: scan ------------------------------------------------
__global__ void scan_kernel(int n) {
    int rel = blockIdx.x;
    __shared__ int sm[1024];
    int tid = threadIdx.x;
    int C = (n + 1023) / 1024;
    int b = tid * C;
    int e = b + C; if (e > n) e = n;
    if (b > n) b = n;
    int s = 0;
    for (int i = b; i < e; i++) s += g_deg[rel][i];
    sm[tid] = s;
    __syncthreads();
#pragma unroll
    for (int ofs = 1; ofs < 1024; ofs <<= 1) {
        int t = (tid >= ofs) ? sm[tid - ofs] : 0;
        __syncthreads();
        sm[tid] += t;
        __syncthreads();
    }
    int run = sm[tid] - s;
    for (int i = b; i < e; i++) { int d = g_deg[rel][i]; g_off[rel][i] = run; run += d; }
    if (e == n) g_off[rel][n] = run;
}

// ---------------- launch 3: scatter ---------------------------------------------
__global__ void scatter2_kernel(const int* __restrict__ e_w, int Ew,
                                const int* __restrict__ e_c, int Ec) {
    int rel = blockIdx.y;
    const int* e = rel ? e_c : e_w;
    int E = rel ? Ec : Ew;
    int i = blockIdx.x * blockDim.x + threadIdx.x;
    if (i < E) {
        int src = e[i];
        int dst = e[E + i];
        int p = atomicAdd(&g_cur[rel][dst], 1);
        g_csr[rel][g_off[rel][dst] + p] = src;
    }
}

// ---------------- launch 4 (PROFILED): tensor-core GEMM, ldmatrix --------------
#define SMS 20
#define AH_W 0
#define AL_W 2560
#define BH_W 5120
#define BL_W 6400
#define STG_W 7680

__device__ __forceinline__ void ldsm_x4(uint32_t addr, uint32_t* r) {
    asm volatile("ldmatrix.sync.aligned.m8n8.x4.shared.b16 {%0,%1,%2,%3}, [%4];"
        : "=r"(r[0]), "=r"(r[1]), "=r"(r[2]), "=r"(r[3]) : "r"(addr));
}

__global__ __launch_bounds__(256, 2) void mma_gemm5(
    const float4* __restrict__ xa4, const float4* __restrict__ xp4, int nrows) {
    extern __shared__ uint32_t dynsm[];
    int slice = blockIdx.z;
    int chalf = blockIdx.y;
    const float4* Xf4 = (slice == 1 || slice == 2) ? xa4 : xp4;
    const uint2* WI = g_wI[slice];

    int tid = threadIdx.x;
    int lane = tid & 31;
    int warp = tid >> 5;
    int wm = warp & 3;
    int wn = warp >> 2;
    int row0 = blockIdx.x * 128;

    float acc[2][4][4];
#pragma unroll
    for (int mt = 0; mt < 2; mt++)
#pragma unroll
        for (int nt = 0; nt < 4; nt++)
#pragma unroll
            for (int r = 0; r < 4; r++) acc[mt][nt][r] = 0.f;

    int lq = lane >> 2;
    int lc = lane & 3;

    int lrow = lane & 7, lsel = lane >> 3;
    uint32_t aoff = (uint32_t)(((lrow + (lsel & 1) * 8) * SMS + (lsel >> 1) * 4) * 4);
    uint32_t boff = (uint32_t)((((lsel >> 1) * 8 + lrow) * SMS) * 4 + (lsel & 1) * 16);

    uint32_t sbase = (uint32_t)__cvta_generic_to_shared(dynsm);

    auto stage = [&](int ch, int stW) {
#pragma unroll
        for (int it = 0; it < 4; it++) {
            int lin = it * 256 + tid;
            int r = lin >> 3, f4 = lin & 7;
            int gr = row0 + r;
            float4 x4 = make_float4(0.f, 0.f, 0.f, 0.f);
            if (gr < nrows) x4 = Xf4[(size_t)gr * 32 + ch * 8 + f4];
            float h0 = __bfloat162float(__float2bfloat16(x4.x));
            float h1 = __bfloat162float(__float2bfloat16(x4.y));
            float h2 = __bfloat162float(__float2bfloat16(x4.z));
            float h3 = __bfloat162float(__float2bfloat16(x4.w));
            *(uint2*)&dynsm[stW + AH_W + r * SMS + f4 * 2] =
                make_uint2(pack_bf2(h0, h1), pack_bf2(h2, h3));
            *(uint2*)&dynsm[stW + AL_W + r * SMS + f4 * 2] =
                make_uint2(pack_bf2(x4.x - h0, x4.y - h1), pack_bf2(x4.z - h2, x4.w - h3));
        }
#pragma unroll
        for (int it = 0; it < 2; it++) {
            int lin = it * 256 + tid;
            int r = lin >> 3, p = lin & 7;
            uint4 w = *(const uint4*)&WI[(size_t)(chalf * 64 + r) * 64 + ch * 16 + p * 2];
            *(uint2*)&dynsm[stW + BH_W + r * SMS + p * 2] = make_uint2(w.x, w.z);
            *(uint2*)&dynsm[stW + BL_W + r * SMS + p * 2] = make_uint2(w.y, w.w);
        }
    };

    stage(0, 0);
    __syncthreads();

#pragma unroll
    for (int ch = 0; ch < 4; ch++) {
        int cur = ch & 1;
        if (ch < 3) stage(ch + 1, (cur ^ 1) * STG_W);

        uint32_t stB = sbase + (uint32_t)(cur * STG_W * 4);
#pragma unroll
        for (int s = 0; s < 2; s++) {
            uint32_t kB = (uint32_t)(s * 32);
            uint32_t ah[2][4], al[2][4];
#pragma unroll
            for (int mt = 0; mt < 2; mt++) {
                uint32_t rB = (uint32_t)((wm * 32 + mt * 16) * SMS * 4);
                ldsm_x4(stB + AH_W * 4 + rB + kB + aoff, ah[mt]);
                ldsm_x4(stB + AL_W * 4 + rB + kB + aoff, al[mt]);
            }
#pragma unroll
            for (int ntp = 0; ntp < 2; ntp++) {
                uint32_t nB = (uint32_t)((wn * 32 + ntp * 16) * SMS * 4);
                uint32_t bh2[4], bl2[4];
                ldsm_x4(stB + BH_W * 4 + nB + kB + boff, bh2);
                ldsm_x4(stB + BL_W * 4 + nB + kB + boff, bl2);
#pragma unroll
                for (int half = 0; half < 2; half++) {
                    int nt = ntp * 2 + half;
                    uint32_t bh0 = bh2[2 * half], bh1 = bh2[2 * half + 1];
                    uint32_t bl0 = bl2[2 * half], bl1 = bl2[2 * half + 1];
#pragma unroll
                    for (int mt = 0; mt < 2; mt++) {
                        float* d = acc[mt][nt];
                        asm volatile(
                            "mma.sync.aligned.m16n8k16.row.col.f32.bf16.bf16.f32 "
                            "{%0,%1,%2,%3}, {%4,%5,%6,%7}, {%8,%9}, {%0,%1,%2,%3};"
                            : "+f"(d[0]), "+f"(d[1]), "+f"(d[2]), "+f"(d[3])
                            : "r"(ah[mt][0]), "r"(ah[mt][1]), "r"(ah[mt][2]), "r"(ah[mt][3]),
                              "r"(bh0), "r"(bh1));
                        asm volatile(
                            "mma.sync.aligned.m16n8k16.row.col.f32.bf16.bf16.f32 "
                            "{%0,%1,%2,%3}, {%4,%5,%6,%7}, {%8,%9}, {%0,%1,%2,%3};"
                            : "+f"(d[0]), "+f"(d[1]), "+f"(d[2]), "+f"(d[3])
                            : "r"(ah[mt][0]), "r"(ah[mt][1]), "r"(ah[mt][2]), "r"(ah[mt][3]),
                              "r"(bl0), "r"(bl1));
                        asm volatile(
                            "mma.sync.aligned.m16n8k16.row.col.f32.bf16.bf16.f32 "
                            "{%0,%1,%2,%3}, {%4,%5,%6,%7}, {%8,%9}, {%0,%1,%2,%3};"
                            : "+f"(d[0]), "+f"(d[1]), "+f"(d[2]), "+f"(d[3])
                            : "r"(al[mt][0]), "r"(al[mt][1]), "r"(al[mt][2]), "r"(al[mt][3]),
                              "r"(bh0), "r"(bh1));
                    }
                }
            }
        }
        __syncthreads();
    }

    if (slice == 0) {
        float* Y = g_qp;
#pragma unroll
        for (int mt = 0; mt < 2; mt++)
#pragma unroll
            for (int nt = 0; nt < 4; nt++) {
                int col = chalf * 64 + wn * 32 + nt * 8 + lc * 2;
                int r0 = row0 + wm * 32 + mt * 16 + lq;
                if (r0 < nrows)
                    *(float2*)(Y + (size_t)r0 * 128 + col) =
                        make_float2(acc[mt][nt][0], acc[mt][nt][1]);
                int r1 = r0 + 8;
                if (r1 < nrows)
                    *(float2*)(Y + (size_t)r1 * 128 + col) =
                        make_float2(acc[mt][nt][2], acc[mt][nt][3]);
            }
    } else {
        __half* Y;
        switch (slice) {
            case 1: Y = g_rkh[0]; break;
            case 2: Y = g_rvh[0]; break;
            case 3: Y = g_rkh[1]; break;
            default:Y = g_rvh[1]; break;
        }
#pragma unroll
        for (int mt = 0; mt < 2; mt++)
#pragma unroll
            for (int nt = 0; nt < 4; nt++) {
                int col = chalf * 64 + wn * 32 + nt * 8 + lc * 2;
                int r0 = row0 + wm * 32 + mt * 16 + lq;
                if (r0 < nrows)
                    *(__half2*)(Y + (size_t)r0 * 128 + col) =
                        __float22half2_rn(make_float2(acc[mt][nt][0], acc[mt][nt][1]));
                int r1 = r0 + 8;
                if (r1 < nrows)
                    *(__half2*)(Y + (size_t)r1 * 128 + col) =
                        __float22half2_rn(make_float2(acc[mt][nt][2], acc[mt][nt][3]));
            }
    }
}

// ---------------- launch 5: aggregation ----------------------------------------
__device__ __forceinline__ float4 half4_to_float4(uint2 u) {
    __half2 h0 = *(__half2*)&u.x;
    __half2 h1 = *(__half2*)&u.y;
    float2 f0 = __half22float2(h0);
    float2 f1 = __half22float2(h1);
    return make_float4(f0.x, f0.y, f1.x, f1.y);
}

__device__ __forceinline__ float head_dot(float4 q4, float4 k4) {
    float p = q4.x*k4.x + q4.y*k4.y + q4.z*k4.z + q4.w*k4.w;
    p += __shfl_xor_sync(0xFFFFFFFFu, p, 1);
    p += __shfl_xor_sync(0xFFFFFFFFu, p, 2);
    p += __shfl_xor_sync(0xFFFFFFFFu, p, 4);
    return p;
}

__device__ __forceinline__ void rel_agg(
    const __half* __restrict__ rk, const __half* __restrict__ rv,
    const int* __restrict__ csr, int beg, int end,
    float4 q4, int lane, float4& acc, float& s) {
    const float scale = 0.17677669529663687f;   // 1/sqrt(32)
    float s0a = 0.f, s1a = 0.f;
    float4 A0 = make_float4(0.f,0.f,0.f,0.f);
    float4 A1 = make_float4(0.f,0.f,0.f,0.f);

    int e = beg;
    for (; e + 4 <= end; e += 4) {
        int i0 = csr[e], i1 = csr[e+1], i2 = csr[e+2], i3 = csr[e+3];
        float4 k0 = half4_to_float4(*(const uint2*)(rk + (size_t)i0 * 128 + lane * 4));
        float4 k1 = half4_to_float4(*(const uint2*)(rk + (size_t)i1 * 128 + lane * 4));
        float4 k2 = half4_to_float4(*(const uint2*)(rk + (size_t)i2 * 128 + lane * 4));
        float4 k3 = half4_to_float4(*(const uint2*)(rk + (size_t)i3 * 128 + lane * 4));
        float4 v0 = half4_to_float4(*(const uint2*)(rv + (size_t)i0 * 128 + lane * 4));
        float4 v1 = half4_to_float4(*(const uint2*)(rv + (size_t)i1 * 128 + lane * 4));
        float4 v2 = half4_to_float4(*(const uint2*)(rv + (size_t)i2 * 128 + lane * 4));
        float4 v3 = half4_to_float4(*(const uint2*)(rv + (size_t)i3 * 128 + lane * 4));
        float p0 = __expf(head_dot(q4, k0) * scale);
        float p1 = __expf(head_dot(q4, k1) * scale);
        float p2 = __expf(head_dot(q4, k2) * scale);
        float p3 = __expf(head_dot(q4, k3) * scale);
        s0a += p0 + p2;
        s1a += p1 + p3;
        A0.x += p0*v0.x + p2*v2.x;  A1.x += p1*v1.x + p3*v3.x;
        A0.y += p0*v0.y + p2*v2.y;  A1.y += p1*v1.y + p3*v3.y;
        A0.z += p0*v0.z + p2*v2.z;  A1.z += p1*v1.z + p3*v3.z;
        A0.w += p0*v0.w + p2*v2.w;  A1.w += p1*v1.w + p3*v3.w;
    }
    for (; e < end; e++) {
        int i0 = csr[e];
        float4 k0 = half4_to_float4(*(const uint2*)(rk + (size_t)i0 * 128 + lane * 4));
        float4 v0 = half4_to_float4(*(const uint2*)(rv + (size_t)i0 * 128 + lane * 4));
        float p0 = __expf(head_dot(q4, k0) * scale);
        s0a += p0;
        A0.x += p0*v0.x; A0.y += p0*v0.y; A0.z += p0*v0.z; A0.w += p0*v0.w;
    }
    s = s0a + s1a;
    acc = make_float4(A0.x + A1.x, A0.y + A1.y, A0.z + A1.z, A0.w + A1.w);
}

__global__ __launch_bounds__(256) void aggregate2_kernel(int n) {
    int warp = (blockIdx.x * blockDim.x + threadIdx.x) >> 5;
    if (warp >= n) return;
    int lane = threadIdx.x & 31;

    float4 q4 = *(const float4*)(g_qp + (size_t)warp * 128 + lane * 4);

    float4 aw, ac;
    float sw, sc;
    int bw = g_off[0][warp], ew = g_off[0][warp + 1];
    int bc = g_off[1][warp], ec = g_off[1][warp + 1];
    rel_agg(g_rkh[0], g_rvh[0], g_csr[0], bw, ew, q4, lane, aw, sw);
    rel_agg(g_rkh[1], g_rvh[1], g_csr[1], bc, ec, q4, lane, ac, sc);

    float iw = (ew > bw) ? 1.f / sw : 0.f;
    float ic = (ec > bc) ? 1.f / sc : 0.f;
    float4 o;
    o.x = aw.x * iw + ac.x * ic;
    o.y = aw.y * iw + ac.y * ic;
    o.z = aw.z * iw + ac.z * ic;
    o.w = aw.w * iw + ac.w * ic;
    *(float4*)(g_outp + (size_t)warp * 128 + lane * 4) = o;
}

// ---------------- launch 6: final projections + counter re-zero ----------------
__global__ __launch_bounds__(256) void final_kernel(
    const float* __restrict__ Xa, const float* __restrict__ Xp,
    const float* __restrict__ Wr_a, const float* __restrict__ Wo_p,
    const float* __restrict__ Wr_p, const float* __restrict__ bo_a,
    const float* __restrict__ bo_p, float* __restrict__ out, int n) {
    int type = blockIdx.y;
    if (type == 2) {
        int i = blockIdx.x * blockDim.x + threadIdx.x;
        if (i < n) {
            g_deg[0][i] = 0; g_deg[1][i] = 0;
            g_cur[0][i] = 0; g_cur[1][i] = 0;
        }
        return;
    }
    __shared__ float Ws[2 * 128 * 32];
    if (type == 0) {
        for (int i = threadIdx.x; i < 4096; i += blockDim.x) Ws[i] = Wr_a[i];
    } else {
        for (int i = threadIdx.x; i < 4096; i += blockDim.x) Ws[i] = Wo_p[i];
        for (int i = threadIdx.x; i < 4096; i += blockDim.x) Ws[4096 + i] = Wr_p[i];
    }
    __syncthreads();
    int warp = blockIdx.x * (blockDim.x >> 5) + (threadIdx.x >> 5);
    int lane = threadIdx.x & 31;
    if (warp >= n) return;

    if (type == 0) {
        const float4* xr4 = (const float4*)(Xa + (size_t)warp * 128);
        float a0 = 0.f, a1 = 0.f;
#pragma unroll
        for (int k4 = 0; k4 < 32; k4++) {
            float4 x4 = xr4[k4];
            a0 += x4.x * Ws[(k4*4+0)*32 + lane] + x4.y * Ws[(k4*4+1)*32 + lane];
            a1 += x4.z * Ws[(k4*4+2)*32 + lane] + x4.w * Ws[(k4*4+3)*32 + lane];
        }
        out[(size_t)warp * 32 + lane] = bo_a[lane] + a0 + a1;
    } else {
        const float4* op4 = (const float4*)(g_outp + (size_t)warp * 128);
        const float4* xr4 = (const float4*)(Xp + (size_t)warp * 128);
        float a0 = 0.f, a1 = 0.f;
#pragma unroll
        for (int k4 = 0; k4 < 32; k4++) {
            float4 x4 = op4[k4];
            a0 += x4.x * Ws[(k4*4+0)*32 + lane] + x4.y * Ws[(k4*4+1)*32 + lane];
            a1 += x4.z * Ws[(k4*4+2)*32 + lane] + x4.w * Ws[(k4*4+3)*32 + lane];
        }
#pragma unroll
        for (int k4 = 0; k4 < 32; k4++) {
            float4 x4 = xr4[k4];
            a0 += x4.x * Ws[4096 + (k4*4+0)*32 + lane] + x4.y * Ws[4096 + (k4*4+1)*32 + lane];
            a1 += x4.z * Ws[4096 + (k4*4+2)*32 + lane] + x4.w * Ws[4096 + (k4*4+3)*32 + lane];
        }
        out[(size_t)(n + warp) * 32 + lane] = bo_p[lane] + a0 + a1;
    }
}

// ---------------- launch --------------------------------------------------------
extern "C" void kernel_launch(void* const* d_in, const int* in_sizes, int n_in,
                              void* d_out, int out_size) {
    const float* x_a   = (const float*)d_in[0];
    const float* x_p   = (const float*)d_in[1];
    const int*   e_w   = (const int*)d_in[2];
    const int*   e_c   = (const int*)d_in[3];
    const float* wk_a  = (const float*)d_in[5];
    const float* wv_a  = (const float*)d_in[6];
    const float* wq_p  = (const float*)d_in[7];
    const float* wk_p  = (const float*)d_in[8];
    const float* wv_p  = (const float*)d_in[9];
    const float* wrk_w = (const float*)d_in[10];
    const float* wrv_w = (const float*)d_in[11];
    const float* wrk_c = (const float*)d_in[12];
    const float* wrv_c = (const float*)d_in[13];
    const float* bo_a  = (const float*)d_in[15];
    const float* wo_p  = (const float*)d_in[16];
    const float* bo_p  = (const float*)d_in[17];
    const float* wr_a  = (const float*)d_in[18];
    const float* wr_p  = (const float*)d_in[19];
    float* out = (float*)d_out;

    int n  = in_sizes[0] / 128;
    int Ew = in_sizes[2] / 2;
    int Ec = in_sizes[3] / 2;

    const int DYN_SMEM = 2 * STG_W * 4;   // 61440 bytes
    cudaFuncSetAttribute(mma_gemm5, cudaFuncAttributeMaxDynamicSharedMemorySize,
                         DYN_SMEM);

    int geb = (((Ew > Ec) ? Ew : Ec) + 255) / 256;
    int gb  = (n + 127) / 128;
    int ga  = (n + 7) / 8;
    int gf  = (n + 7) / 8;

    // 1: hist + compose/weight-split
    fusedA_kernel<<<dim3(geb, 2, 2), 256>>>(e_w, Ew, e_c, Ec, wq_p,
                                            wk_a, wv_a, wk_p, wv_p,
                                            wrk_w, wrv_w, wrk_c, wrv_c);
    // 2: scan
    scan_kernel<<<2, 1024>>>(n);
    // 3: scatter
    scatter2_kernel<<<dim3(geb, 2), 256>>>(e_w, Ew, e_c, Ec);
    // 4 (profiled): GEMMs
    mma_gemm5<<<dim3(gb, 2, 5), 256, DYN_SMEM>>>((const float4*)x_a,
                                                 (const float4*)x_p, n);
    // 5: aggregation
    aggregate2_kernel<<<ga, 256>>>(n);
    // 6: final + counter re-zero
    final_kernel<<<dim3(gf, 3), 256>>>(x_a, x_p, wr_a, wo_p, wr_p,
                                       bo_a, bo_p, out, n);
}